// round 3
// baseline (speedup 1.0000x reference)
#include <cuda_runtime.h>
#include <cuda_bf16.h>
#include <cstdint>
#include <cstdio>

// ---------------------------------------------------------------------------
// AtomAttentionPairBias: B=1, Nq=Nk=4096, C=128, H=4, c=32, CZ=16  (all fp32)
//
// Plan:
//   1. ln_kernel (x2): LN(a) and LN(s)*sscale per row.
//   2. dual_gemm<ADALN> (x2): aq = sigmoid(sn@Wg+bg)*LN(a) + sn@Wb
//   3. dual_gemm<QG>: q = (aq@Wq+bq)*scale ; g = sigmoid(aq@Wgate)
//   4. dual_gemm<KV>: k = ak@Wk ; v = ak@Wv
//   5. attn_kernel: flash attention, z-bias fused (z streamed ONCE),
//      QK^T and PV via tf32 mma.sync; epilogue applies gate g -> og
//   6. dual_gemm<FINAL>: out = sigmoid(s_q@Ws+bs) * (og@Wo)
// ---------------------------------------------------------------------------

#define NSEQ 4096
#define CDIM 128
#define NHEAD 4
#define HDIM 32
#define CZ 16
#define EPS 1e-5f
#define QK_SCALE 0.17677669529663687f   // 1/sqrt(32)

// scratch: 11 slices of [4096 x 128] fp32
__device__ float g_scratch[11u * NSEQ * CDIM];

__constant__ float c_wb[CZ * NHEAD];  // Wbias (row-major [cz][h])
__constant__ float c_lnz[CZ];         // lnz_scale

__device__ __forceinline__ float sigmoidf_(float x) { return 1.f / (1.f + __expf(-x)); }

// ------------------------------ LN kernel ---------------------------------
__global__ void ln_kernel(const float* __restrict__ a, const float* __restrict__ s,
                          const float* __restrict__ sscale,
                          float* __restrict__ lnA, float* __restrict__ sn) {
    int warp = threadIdx.x >> 5, lane = threadIdx.x & 31;
    int row = blockIdx.x * 8 + warp;
    if (row >= NSEQ) return;
    const float4* ap = (const float4*)(a + (size_t)row * CDIM);
    const float4* sp = (const float4*)(s + (size_t)row * CDIM);
    float4 av = ap[lane];
    float4 sv = sp[lane];

    float s1 = av.x + av.y + av.z + av.w;
    float s2 = av.x*av.x + av.y*av.y + av.z*av.z + av.w*av.w;
    float t1 = sv.x + sv.y + sv.z + sv.w;
    float t2 = sv.x*sv.x + sv.y*sv.y + sv.z*sv.z + sv.w*sv.w;
    #pragma unroll
    for (int o = 16; o > 0; o >>= 1) {
        s1 += __shfl_xor_sync(~0u, s1, o);
        s2 += __shfl_xor_sync(~0u, s2, o);
        t1 += __shfl_xor_sync(~0u, t1, o);
        t2 += __shfl_xor_sync(~0u, t2, o);
    }
    float ma = s1 * (1.f/CDIM);
    float ra = rsqrtf(s2 * (1.f/CDIM) - ma*ma + EPS);
    float ms = t1 * (1.f/CDIM);
    float rs = rsqrtf(t2 * (1.f/CDIM) - ms*ms + EPS);

    float4 sc = ((const float4*)sscale)[lane];
    float4 oa, os;
    oa.x = (av.x - ma) * ra; oa.y = (av.y - ma) * ra;
    oa.z = (av.z - ma) * ra; oa.w = (av.w - ma) * ra;
    os.x = (sv.x - ms) * rs * sc.x; os.y = (sv.y - ms) * rs * sc.y;
    os.z = (sv.z - ms) * rs * sc.z; os.w = (sv.w - ms) * rs * sc.w;
    ((float4*)(lnA + (size_t)row * CDIM))[lane] = oa;
    ((float4*)(sn  + (size_t)row * CDIM))[lane] = os;
}

// --------------------------- dual GEMM kernel ------------------------------
// acc1 = X1@W1 , acc2 = X2@W2 over [32 rows x 128 cols] per block.
#define MODE_ADALN 0
#define MODE_QG    1
#define MODE_KV    2
#define MODE_FINAL 3

template<int MODE>
__global__ __launch_bounds__(256) void dual_gemm(
    const float* __restrict__ X1, const float* __restrict__ X2,
    const float* __restrict__ W1, const float* __restrict__ W2,
    const float* __restrict__ b1, const float* __restrict__ b2,
    const float* __restrict__ E,
    float* __restrict__ out1, float* __restrict__ out2) {

    __shared__ float sX1[32][16];
    __shared__ float sX2[32][16];
    __shared__ float sW1[16][128];
    __shared__ float sW2[16][128];

    int tid = threadIdx.x;
    int row0 = blockIdx.x * 32;
    int ty = tid >> 4;   // 0..15 -> rows {ty, ty+16}
    int tx = tid & 15;   // 0..15 -> cols {tx + 16*j}

    float acc1[2][8], acc2[2][8];
    #pragma unroll
    for (int i = 0; i < 2; i++)
        #pragma unroll
        for (int j = 0; j < 8; j++) { acc1[i][j] = 0.f; acc2[i][j] = 0.f; }

    for (int kc = 0; kc < CDIM; kc += 16) {
        #pragma unroll
        for (int i = 0; i < 2; i++) {
            int e = tid + i * 256;
            int r = e >> 4, kk = e & 15;
            sX1[r][kk] = X1[(size_t)(row0 + r) * CDIM + kc + kk];
            sX2[r][kk] = X2[(size_t)(row0 + r) * CDIM + kc + kk];
        }
        #pragma unroll
        for (int i = 0; i < 8; i++) {
            int e = tid + i * 256;
            int kk = e >> 7, c = e & 127;
            sW1[kk][c] = W1[(size_t)(kc + kk) * CDIM + c];
            sW2[kk][c] = W2[(size_t)(kc + kk) * CDIM + c];
        }
        __syncthreads();
        #pragma unroll
        for (int kk = 0; kk < 16; kk++) {
            float x1a = sX1[ty][kk],      x1b = sX1[ty + 16][kk];
            float x2a = sX2[ty][kk],      x2b = sX2[ty + 16][kk];
            #pragma unroll
            for (int j = 0; j < 8; j++) {
                float w1 = sW1[kk][tx + 16 * j];
                float w2 = sW2[kk][tx + 16 * j];
                acc1[0][j] += x1a * w1; acc1[1][j] += x1b * w1;
                acc2[0][j] += x2a * w2; acc2[1][j] += x2b * w2;
            }
        }
        __syncthreads();
    }

    #pragma unroll
    for (int i = 0; i < 2; i++) {
        int r = row0 + ty + i * 16;
        #pragma unroll
        for (int j = 0; j < 8; j++) {
            int cc = tx + 16 * j;
            size_t idx = (size_t)r * CDIM + cc;
            if (MODE == MODE_ADALN) {
                float gsig = sigmoidf_(acc1[i][j] + b1[cc]);
                out1[idx] = gsig * E[idx] + acc2[i][j];
            } else if (MODE == MODE_QG) {
                out1[idx] = (acc1[i][j] + b1[cc]) * QK_SCALE;
                out2[idx] = sigmoidf_(acc2[i][j]);
            } else if (MODE == MODE_KV) {
                out1[idx] = acc1[i][j];
                out2[idx] = acc2[i][j];
            } else { // FINAL
                out1[idx] = sigmoidf_(acc2[i][j] + b2[cc]) * acc1[i][j];
            }
        }
    }
}

// --------------------------- attention kernel ------------------------------
#define K_STRIDE 132
#define V_STRIDE 136
#define P_STRIDE 68
#define SMEM_FLOATS (64 * K_STRIDE + 64 * V_STRIDE + NHEAD * 32 * P_STRIDE)
#define SMEM_BYTES  (SMEM_FLOATS * 4)

__device__ __forceinline__ uint32_t f2tf32(float x) {
    uint32_t y; asm("cvt.rna.tf32.f32 %0, %1;" : "=r"(y) : "f"(x)); return y;
}
__device__ __forceinline__ void mma_tf32(float* d, const uint32_t* a, const uint32_t* b) {
    asm volatile("mma.sync.aligned.m16n8k8.row.col.f32.tf32.tf32.f32 "
                 "{%0,%1,%2,%3}, {%4,%5,%6,%7}, {%8,%9}, {%0,%1,%2,%3};"
                 : "+f"(d[0]), "+f"(d[1]), "+f"(d[2]), "+f"(d[3])
                 : "r"(a[0]), "r"(a[1]), "r"(a[2]), "r"(a[3]), "r"(b[0]), "r"(b[1]));
}
__device__ __forceinline__ void cp16(float* dst, const float* src) {
    uint32_t d = (uint32_t)__cvta_generic_to_shared(dst);
    asm volatile("cp.async.cg.shared.global [%0], [%1], 16;" :: "r"(d), "l"(src));
}

__global__ __launch_bounds__(256, 1) void attn_kernel(
    const float* __restrict__ z,
    const float* __restrict__ gq, const float* __restrict__ gk,
    const float* __restrict__ gv, const float* __restrict__ gg,
    float* __restrict__ og) {

    extern __shared__ float smem[];
    float* Ksm = smem;
    float* Vsm = smem + 64 * K_STRIDE;
    float* Psm = Vsm + 64 * V_STRIDE;

    const int tid  = threadIdx.x;
    const int lane = tid & 31, warp = tid >> 5;
    const int h = warp >> 1, qh = warp & 1;
    const int gid = lane >> 2, ctg = lane & 3;
    const int qg0 = blockIdx.x * 32;

    // colsum_h = sum_c lnz[c]*Wbias[c][h]   (constants -> identical per thread)
    float csum0 = 0.f, csum1 = 0.f, csum2 = 0.f, csum3 = 0.f;
    #pragma unroll
    for (int c = 0; c < CZ; c++) {
        float l = c_lnz[c];
        csum0 += l * c_wb[c*4+0]; csum1 += l * c_wb[c*4+1];
        csum2 += l * c_wb[c*4+2]; csum3 += l * c_wb[c*4+3];
    }

    // Q fragments (A of m16n8k8 tf32), q is pre-scaled by 1/sqrt(c)
    uint32_t qa[4][4];
    {
        int r0 = qg0 + qh * 16 + gid;
        const float* qp = gq + (size_t)r0 * CDIM + h * HDIM + ctg;
        #pragma unroll
        for (int ks = 0; ks < 4; ks++) {
            qa[ks][0] = f2tf32(qp[ks*8]);
            qa[ks][1] = f2tf32(qp[8*CDIM + ks*8]);
            qa[ks][2] = f2tf32(qp[ks*8 + 4]);
            qa[ks][3] = f2tf32(qp[8*CDIM + ks*8 + 4]);
        }
    }

    float O[4][4];
    #pragma unroll
    for (int i = 0; i < 4; i++) { O[i][0]=O[i][1]=O[i][2]=O[i][3]=0.f; }
    float m1 = -1e30f, m2 = -1e30f, l1 = 0.f, l2 = 0.f;

    const int kk0 = tid & 63;   // key within tile for bias phase
    const int qq0 = tid >> 6;   // base q row (0..3) for bias phase

    for (int kb = 0; kb < NSEQ; kb += 64) {
        __syncthreads();   // previous tile fully consumed

        // ---- prefetch K/V tile into smem (cp.async; overlaps with z stream)
        #pragma unroll
        for (int i = 0; i < 8; i++) {
            int e = tid + i * 256;
            int r = e >> 5, c4 = e & 31;
            cp16(Ksm + r * K_STRIDE + c4 * 4, gk + (size_t)(kb + r) * CDIM + c4 * 4);
        }
        #pragma unroll
        for (int i = 0; i < 8; i++) {
            int e = tid + i * 256;
            int r = e >> 5, c4 = e & 31;
            cp16(Vsm + r * V_STRIDE + c4 * 4, gv + (size_t)(kb + r) * CDIM + c4 * 4);
        }
        asm volatile("cp.async.commit_group;" ::: "memory");

        // ---- bias phase: LN(z)@Wbias fused, 8 (q,k) pairs per thread
        {
            float4 zb0, zb1, zb2, zb3;
            {
                const float4* zp = (const float4*)(z + ((size_t)(qg0 + qq0) * NSEQ + kb + kk0) * CZ);
                zb0 = zp[0]; zb1 = zp[1]; zb2 = zp[2]; zb3 = zp[3];
            }
            #pragma unroll
            for (int qi = 0; qi < 8; qi++) {
                float4 zc[4] = { zb0, zb1, zb2, zb3 };
                if (qi < 7) {
                    const float4* zn = (const float4*)(z + ((size_t)(qg0 + qq0 + (qi+1)*4) * NSEQ + kb + kk0) * CZ);
                    zb0 = zn[0]; zb1 = zn[1]; zb2 = zn[2]; zb3 = zn[3];
                }
                float s1 = 0.f, s2 = 0.f, d0 = 0.f, d1 = 0.f, d2 = 0.f, d3 = 0.f;
                #pragma unroll
                for (int j = 0; j < 4; j++) {
                    float4 v = zc[j];
                    int cb = j * 4;
                    s1 += v.x + v.y + v.z + v.w;
                    s2 += v.x*v.x + v.y*v.y + v.z*v.z + v.w*v.w;
                    float zl;
                    zl = v.x * c_lnz[cb+0];
                    d0 += zl*c_wb[(cb+0)*4+0]; d1 += zl*c_wb[(cb+0)*4+1];
                    d2 += zl*c_wb[(cb+0)*4+2]; d3 += zl*c_wb[(cb+0)*4+3];
                    zl = v.y * c_lnz[cb+1];
                    d0 += zl*c_wb[(cb+1)*4+0]; d1 += zl*c_wb[(cb+1)*4+1];
                    d2 += zl*c_wb[(cb+1)*4+2]; d3 += zl*c_wb[(cb+1)*4+3];
                    zl = v.z * c_lnz[cb+2];
                    d0 += zl*c_wb[(cb+2)*4+0]; d1 += zl*c_wb[(cb+2)*4+1];
                    d2 += zl*c_wb[(cb+2)*4+2]; d3 += zl*c_wb[(cb+2)*4+3];
                    zl = v.w * c_lnz[cb+3];
                    d0 += zl*c_wb[(cb+3)*4+0]; d1 += zl*c_wb[(cb+3)*4+1];
                    d2 += zl*c_wb[(cb+3)*4+2]; d3 += zl*c_wb[(cb+3)*4+3];
                }
                float mm = s1 * (1.f/CZ);
                float var = s2 * (1.f/CZ) - mm * mm;
                float rstd = rsqrtf(var + EPS);
                int q = qq0 + qi * 4;
                float* pb = Psm + q * P_STRIDE + kk0;
                pb[0 * 32 * P_STRIDE] = (d0 - mm * csum0) * rstd;
                pb[1 * 32 * P_STRIDE] = (d1 - mm * csum1) * rstd;
                pb[2 * 32 * P_STRIDE] = (d2 - mm * csum2) * rstd;
                pb[3 * 32 * P_STRIDE] = (d3 - mm * csum3) * rstd;
            }
        }
        asm volatile("cp.async.wait_group 0;" ::: "memory");
        __syncthreads();   // bias + K/V visible to everyone

        // ---- QK^T (tf32 mma): S[16q x 64k] per warp
        float S[8][4];
        #pragma unroll
        for (int nt = 0; nt < 8; nt++) {
            S[nt][0] = S[nt][1] = S[nt][2] = S[nt][3] = 0.f;
            const float* kp = Ksm + (nt * 8 + gid) * K_STRIDE + h * HDIM + ctg;
            #pragma unroll
            for (int ks = 0; ks < 4; ks++) {
                uint32_t b[2];
                b[0] = __float_as_uint(kp[ks * 8]);
                b[1] = __float_as_uint(kp[ks * 8 + 4]);
                mma_tf32(S[nt], qa[ks], b);
            }
        }

        // ---- bias add + online softmax
        float* pwarp = Psm + h * 32 * P_STRIDE + (qh * 16) * P_STRIDE;
        float mx1 = -1e30f, mx2 = -1e30f;
        #pragma unroll
        for (int nt = 0; nt < 8; nt++) {
            int col = nt * 8 + 2 * ctg;
            S[nt][0] += pwarp[gid * P_STRIDE + col];
            S[nt][1] += pwarp[gid * P_STRIDE + col + 1];
            S[nt][2] += pwarp[(gid + 8) * P_STRIDE + col];
            S[nt][3] += pwarp[(gid + 8) * P_STRIDE + col + 1];
            mx1 = fmaxf(mx1, fmaxf(S[nt][0], S[nt][1]));
            mx2 = fmaxf(mx2, fmaxf(S[nt][2], S[nt][3]));
        }
        mx1 = fmaxf(mx1, __shfl_xor_sync(~0u, mx1, 1));
        mx1 = fmaxf(mx1, __shfl_xor_sync(~0u, mx1, 2));
        mx2 = fmaxf(mx2, __shfl_xor_sync(~0u, mx2, 1));
        mx2 = fmaxf(mx2, __shfl_xor_sync(~0u, mx2, 2));
        float mn1 = fmaxf(m1, mx1), mn2 = fmaxf(m2, mx2);
        float al1 = __expf(m1 - mn1), al2 = __expf(m2 - mn2);
        float rs1 = 0.f, rs2 = 0.f;
        #pragma unroll
        for (int nt = 0; nt < 8; nt++) {
            float p0 = __expf(S[nt][0] - mn1);
            float p1 = __expf(S[nt][1] - mn1);
            float p2 = __expf(S[nt][2] - mn2);
            float p3 = __expf(S[nt][3] - mn2);
            rs1 += p0 + p1; rs2 += p2 + p3;
            int col = nt * 8 + 2 * ctg;
            pwarp[gid * P_STRIDE + col]           = __uint_as_float(f2tf32(p0));
            pwarp[gid * P_STRIDE + col + 1]       = __uint_as_float(f2tf32(p1));
            pwarp[(gid + 8) * P_STRIDE + col]     = __uint_as_float(f2tf32(p2));
            pwarp[(gid + 8) * P_STRIDE + col + 1] = __uint_as_float(f2tf32(p3));
        }
        rs1 += __shfl_xor_sync(~0u, rs1, 1); rs1 += __shfl_xor_sync(~0u, rs1, 2);
        rs2 += __shfl_xor_sync(~0u, rs2, 1); rs2 += __shfl_xor_sync(~0u, rs2, 2);
        l1 = l1 * al1 + rs1; l2 = l2 * al2 + rs2;
        m1 = mn1; m2 = mn2;
        #pragma unroll
        for (int on = 0; on < 4; on++) {
            O[on][0] *= al1; O[on][1] *= al1; O[on][2] *= al2; O[on][3] *= al2;
        }
        __syncwarp();

        // ---- PV (tf32 mma): O[16q x 32c] += P[16q x 64k] @ V[64k x 32c]
        #pragma unroll
        for (int on = 0; on < 4; on++) {
            #pragma unroll
            for (int ks = 0; ks < 8; ks++) {
                uint32_t a[4], b[2];
                const float* pp = pwarp + gid * P_STRIDE + ks * 8 + ctg;
                a[0] = __float_as_uint(pp[0]);
                a[1] = __float_as_uint(pp[8 * P_STRIDE]);
                a[2] = __float_as_uint(pp[4]);
                a[3] = __float_as_uint(pp[8 * P_STRIDE + 4]);
                const float* vp = Vsm + (ks * 8 + ctg) * V_STRIDE + h * HDIM + on * 8 + gid;
                b[0] = __float_as_uint(vp[0]);
                b[1] = __float_as_uint(vp[4 * V_STRIDE]);
                mma_tf32(O[on], a, b);
            }
        }
    }

    // ---- epilogue: normalize, gate, store
    float r1 = 1.f / l1, r2 = 1.f / l2;
    int row1 = qg0 + qh * 16 + gid, row2 = row1 + 8;
    #pragma unroll
    for (int on = 0; on < 4; on++) {
        int col = h * HDIM + on * 8 + 2 * ctg;
        size_t i1 = (size_t)row1 * CDIM + col;
        size_t i2 = (size_t)row2 * CDIM + col;
        og[i1]     = O[on][0] * r1 * gg[i1];
        og[i1 + 1] = O[on][1] * r1 * gg[i1 + 1];
        og[i2]     = O[on][2] * r2 * gg[i2];
        og[i2 + 1] = O[on][3] * r2 * gg[i2 + 1];
    }
}

// ------------------------------ launch -------------------------------------
extern "C" void kernel_launch(void* const* d_in, const int* in_sizes, int n_in,
                              void* d_out, int out_size) {
    const float* a_q      = (const float*)d_in[0];
    const float* a_k      = (const float*)d_in[1];
    const float* z        = (const float*)d_in[2];
    const float* s_q      = (const float*)d_in[3];
    const float* s_k      = (const float*)d_in[4];
    const float* Wg_q     = (const float*)d_in[5];
    const float* bg_q     = (const float*)d_in[6];
    const float* Wb_q     = (const float*)d_in[7];
    const float* sscale_q = (const float*)d_in[8];
    const float* Wg_k     = (const float*)d_in[9];
    const float* bg_k     = (const float*)d_in[10];
    const float* Wb_k     = (const float*)d_in[11];
    const float* sscale_k = (const float*)d_in[12];
    const float* lnz      = (const float*)d_in[13];
    const float* Wq       = (const float*)d_in[14];
    const float* bq       = (const float*)d_in[15];
    const float* Wk       = (const float*)d_in[16];
    const float* Wv       = (const float*)d_in[17];
    const float* Wbias    = (const float*)d_in[18];
    const float* Wgate    = (const float*)d_in[19];
    const float* Wo       = (const float*)d_in[20];
    const float* Ws       = (const float*)d_in[21];
    const float* bs       = (const float*)d_in[22];

    float* scratch = nullptr;
    cudaGetSymbolAddress((void**)&scratch, g_scratch);
    const size_t SL = (size_t)NSEQ * CDIM;
    float* lnA_q = scratch + 0 * SL;
    float* sn_q  = scratch + 1 * SL;
    float* lnA_k = scratch + 2 * SL;
    float* sn_k  = scratch + 3 * SL;
    float* aq    = scratch + 4 * SL;
    float* ak    = scratch + 5 * SL;
    float* qbuf  = scratch + 6 * SL;
    float* gbuf  = scratch + 7 * SL;
    float* kbuf  = scratch + 8 * SL;
    float* vbuf  = scratch + 9 * SL;
    float* ogbuf = scratch + 10 * SL;

    cudaMemcpyToSymbolAsync(c_wb, Wbias, CZ * NHEAD * sizeof(float), 0,
                            cudaMemcpyDeviceToDevice, 0);
    cudaMemcpyToSymbolAsync(c_lnz, lnz, CZ * sizeof(float), 0,
                            cudaMemcpyDeviceToDevice, 0);

    ln_kernel<<<NSEQ / 8, 256>>>(a_q, s_q, sscale_q, lnA_q, sn_q);
    ln_kernel<<<NSEQ / 8, 256>>>(a_k, s_k, sscale_k, lnA_k, sn_k);

    dual_gemm<MODE_ADALN><<<NSEQ / 32, 256>>>(sn_q, sn_q, Wg_q, Wb_q, bg_q, nullptr,
                                              lnA_q, aq, nullptr);
    dual_gemm<MODE_ADALN><<<NSEQ / 32, 256>>>(sn_k, sn_k, Wg_k, Wb_k, bg_k, nullptr,
                                              lnA_k, ak, nullptr);
    dual_gemm<MODE_QG><<<NSEQ / 32, 256>>>(aq, aq, Wq, Wgate, bq, nullptr,
                                           nullptr, qbuf, gbuf);
    dual_gemm<MODE_KV><<<NSEQ / 32, 256>>>(ak, ak, Wk, Wv, nullptr, nullptr,
                                           nullptr, kbuf, vbuf);

    cudaFuncSetAttribute(attn_kernel, cudaFuncAttributeMaxDynamicSharedMemorySize,
                         SMEM_BYTES);
    attn_kernel<<<NSEQ / 32, 256, SMEM_BYTES>>>(z, qbuf, kbuf, vbuf, gbuf, ogbuf);

    dual_gemm<MODE_FINAL><<<NSEQ / 32, 256>>>(ogbuf, s_q, Wo, Ws, nullptr, bs,
                                              nullptr, (float*)d_out, nullptr);
}

// round 4
// speedup vs baseline: 1.0982x; 1.0982x over previous
#include <cuda_runtime.h>
#include <cuda_bf16.h>
#include <cstdint>
#include <cstdio>

// ---------------------------------------------------------------------------
// AtomAttentionPairBias: B=1, Nq=Nk=4096, C=128, H=4, c=32, CZ=16  (all fp32)
//
//   1. init_bias: premultiply lnz*Wbias -> constant bank
//   2. side_kernel<Q/K>: LN -> AdaLN -> {q,gate} / {k,v}; all GEMMs via
//      split-tf32 (hi/lo, 3 mma) tensor-core math, chained in-block via smem
//   3. attn_kernel: flash attention, z-bias fused (z streamed ONCE),
//      tf32 mma for QK^T and PV, cross-tile z prefetch
//   4. final_kernel: out = sigmoid(s_q@Ws+bs) * (og@Wo), split-tf32
// ---------------------------------------------------------------------------

#define NSEQ 4096
#define CDIM 128
#define NHEAD 4
#define HDIM 32
#define CZ 16
#define EPS 1e-5f
#define QK_SCALE 0.17677669529663687f   // 1/sqrt(32)

__device__ float g_scratch[6u * NSEQ * CDIM];

// c_bias[0..63]  = lnz[c] * Wbias[c][h]  (row-major [cz][h])
// c_bias[64..67] = per-head column sums of the above
__constant__ float c_bias[CZ * NHEAD + NHEAD];

__device__ __forceinline__ float sigmoidf_(float x) { return 1.f / (1.f + __expf(-x)); }

__device__ __forceinline__ uint32_t f2tf32(float x) {
    uint32_t y; asm("cvt.rna.tf32.f32 %0, %1;" : "=r"(y) : "f"(x)); return y;
}
__device__ __forceinline__ void mma_tf32(float* d, const uint32_t* a, const uint32_t* b) {
    asm volatile("mma.sync.aligned.m16n8k8.row.col.f32.tf32.tf32.f32 "
                 "{%0,%1,%2,%3}, {%4,%5,%6,%7}, {%8,%9}, {%0,%1,%2,%3};"
                 : "+f"(d[0]), "+f"(d[1]), "+f"(d[2]), "+f"(d[3])
                 : "r"(a[0]), "r"(a[1]), "r"(a[2]), "r"(a[3]), "r"(b[0]), "r"(b[1]));
}
__device__ __forceinline__ void cp16(float* dst, const float* src) {
    uint32_t d = (uint32_t)__cvta_generic_to_shared(dst);
    asm volatile("cp.async.cg.shared.global [%0], [%1], 16;" :: "r"(d), "l"(src));
}

// ------------------------------ init_bias ----------------------------------
__global__ void init_bias(const float* __restrict__ lnz, const float* __restrict__ wb,
                          float* __restrict__ out) {
    int t = threadIdx.x;
    if (t < 64) out[t] = lnz[t >> 2] * wb[t];
    if (t >= 64 && t < 68) {
        int h = t - 64;
        float s = 0.f;
        for (int c = 0; c < CZ; c++) s += lnz[c] * wb[c * 4 + h];
        out[t] = s;
    }
}

// ------------------- split-tf32 dual GEMM tile helper -----------------------
// Block computes [32 rows x 128 cols] for TWO GEMMs:
//   acc1 = A1[32x128] @ W1[128x128],  acc2 = A2[32x128] @ W2[128x128]
// A tiles live in smem with row stride 132 (fp32). W streamed via smem chunks
// of 64 k-rows, stride 136. Split-tf32: x = hi + lo; D += hi*Bhi + hi*Blo + lo*Bhi.
// Warp w: rows r0=(w&1)*16, cols c0=(w>>1)*32. Accumulator layout (m16n8):
//   acc[nt][0]=D[gid][2ctg] acc[nt][1]=D[gid][2ctg+1] acc[nt][2..3]=rows gid+8.
#define SA_STRIDE 132
#define SW_STRIDE 136

template<bool SAME_A>
__device__ __forceinline__ void gemm_dual(
    const float* __restrict__ sA1, const float* __restrict__ sA2,
    const float* __restrict__ gW1, const float* __restrict__ gW2,
    float* sW, int tid, float acc1[4][4], float acc2[4][4]) {

    const int lane = tid & 31, warp = tid >> 5;
    const int gid = lane >> 2, ctg = lane & 3;
    const int r0 = (warp & 1) * 16;
    const int c0 = (warp >> 1) * 32;

    #pragma unroll
    for (int nt = 0; nt < 4; nt++)
        #pragma unroll
        for (int j = 0; j < 4; j++) { acc1[nt][j] = 0.f; acc2[nt][j] = 0.f; }

    for (int kc = 0; kc < CDIM; kc += 64) {
        __syncthreads();   // protect sW from previous chunk's readers
        #pragma unroll
        for (int i = 0; i < 8; i++) {
            int e = tid + i * 256;
            int r = e >> 5, c4 = e & 31;
            cp16(sW + r * SW_STRIDE + c4 * 4, gW1 + (size_t)(kc + r) * CDIM + c4 * 4);
            cp16(sW + 64 * SW_STRIDE + r * SW_STRIDE + c4 * 4,
                 gW2 + (size_t)(kc + r) * CDIM + c4 * 4);
        }
        asm volatile("cp.async.commit_group;\ncp.async.wait_group 0;" ::: "memory");
        __syncthreads();

        #pragma unroll
        for (int ks = 0; ks < 8; ks++) {
            int kg = kc + ks * 8;
            uint32_t a1h[4], a1l[4], a2h[4], a2l[4];
            {
                const float* ap = sA1 + (r0 + gid) * SA_STRIDE + kg + ctg;
                float x;
                x = ap[0];               a1h[0] = f2tf32(x); a1l[0] = f2tf32(x - __uint_as_float(a1h[0]));
                x = ap[8 * SA_STRIDE];   a1h[1] = f2tf32(x); a1l[1] = f2tf32(x - __uint_as_float(a1h[1]));
                x = ap[4];               a1h[2] = f2tf32(x); a1l[2] = f2tf32(x - __uint_as_float(a1h[2]));
                x = ap[8 * SA_STRIDE+4]; a1h[3] = f2tf32(x); a1l[3] = f2tf32(x - __uint_as_float(a1h[3]));
            }
            if (!SAME_A) {
                const float* ap = sA2 + (r0 + gid) * SA_STRIDE + kg + ctg;
                float x;
                x = ap[0];               a2h[0] = f2tf32(x); a2l[0] = f2tf32(x - __uint_as_float(a2h[0]));
                x = ap[8 * SA_STRIDE];   a2h[1] = f2tf32(x); a2l[1] = f2tf32(x - __uint_as_float(a2h[1]));
                x = ap[4];               a2h[2] = f2tf32(x); a2l[2] = f2tf32(x - __uint_as_float(a2h[2]));
                x = ap[8 * SA_STRIDE+4]; a2h[3] = f2tf32(x); a2l[3] = f2tf32(x - __uint_as_float(a2h[3]));
            }
            #pragma unroll
            for (int nt = 0; nt < 4; nt++) {
                const float* bp = sW + (ks * 8 + ctg) * SW_STRIDE + c0 + nt * 8 + gid;
                uint32_t bh[2], bl[2];
                float b0 = bp[0], b1 = bp[4 * SW_STRIDE];
                bh[0] = f2tf32(b0); bl[0] = f2tf32(b0 - __uint_as_float(bh[0]));
                bh[1] = f2tf32(b1); bl[1] = f2tf32(b1 - __uint_as_float(bh[1]));
                mma_tf32(acc1[nt], a1h, bh);
                mma_tf32(acc1[nt], a1h, bl);
                mma_tf32(acc1[nt], a1l, bh);
                const float* bp2 = bp + 64 * SW_STRIDE;
                b0 = bp2[0]; b1 = bp2[4 * SW_STRIDE];
                bh[0] = f2tf32(b0); bl[0] = f2tf32(b0 - __uint_as_float(bh[0]));
                bh[1] = f2tf32(b1); bl[1] = f2tf32(b1 - __uint_as_float(bh[1]));
                if (SAME_A) {
                    mma_tf32(acc2[nt], a1h, bh);
                    mma_tf32(acc2[nt], a1h, bl);
                    mma_tf32(acc2[nt], a1l, bh);
                } else {
                    mma_tf32(acc2[nt], a2h, bh);
                    mma_tf32(acc2[nt], a2h, bl);
                    mma_tf32(acc2[nt], a2l, bh);
                }
            }
        }
    }
}

#define SMEM_SIDE_FLOATS (2 * 32 * SA_STRIDE + 2 * 64 * SW_STRIDE)
#define SMEM_SIDE_BYTES  (SMEM_SIDE_FLOATS * 4)

// ------------------------------ side kernel --------------------------------
// SIDE=0 (q): out1 = (aq@Wq + bq)*QK_SCALE ; out2 = sigmoid(aq@Wgate)
// SIDE=1 (k): out1 = ak@Wk               ; out2 = ak@Wv
template<int SIDE>
__global__ __launch_bounds__(256) void side_kernel(
    const float* __restrict__ ga, const float* __restrict__ gs,
    const float* __restrict__ sscale,
    const float* __restrict__ Wg, const float* __restrict__ bg,
    const float* __restrict__ Wb,
    const float* __restrict__ W1, const float* __restrict__ b1,
    const float* __restrict__ W2,
    float* __restrict__ out1, float* __restrict__ out2) {

    extern __shared__ float smem[];
    float* sA = smem;                     // LN(a)
    float* sS = smem + 32 * SA_STRIDE;    // LN(s)*sscale, later aq
    float* sW = smem + 2 * 32 * SA_STRIDE;

    const int tid = threadIdx.x;
    const int lane = tid & 31, warp = tid >> 5;
    const int gid = lane >> 2, ctg = lane & 3;
    const int r0 = (warp & 1) * 16;
    const int c0 = (warp >> 1) * 32;
    const int row0 = blockIdx.x * 32;

    // ---- phase A: LN(a), LN(s)*sscale  (warp per row, 4 passes)
    {
        float4 sc = ((const float4*)sscale)[lane];
        #pragma unroll
        for (int rr = 0; rr < 4; rr++) {
            int lrow = rr * 8 + warp;
            const float4* ap = (const float4*)(ga + (size_t)(row0 + lrow) * CDIM);
            const float4* sp = (const float4*)(gs + (size_t)(row0 + lrow) * CDIM);
            float4 av = ap[lane];
            float4 sv = sp[lane];
            float s1 = av.x + av.y + av.z + av.w;
            float s2 = av.x*av.x + av.y*av.y + av.z*av.z + av.w*av.w;
            float t1 = sv.x + sv.y + sv.z + sv.w;
            float t2 = sv.x*sv.x + sv.y*sv.y + sv.z*sv.z + sv.w*sv.w;
            #pragma unroll
            for (int o = 16; o > 0; o >>= 1) {
                s1 += __shfl_xor_sync(~0u, s1, o);
                s2 += __shfl_xor_sync(~0u, s2, o);
                t1 += __shfl_xor_sync(~0u, t1, o);
                t2 += __shfl_xor_sync(~0u, t2, o);
            }
            float ma = s1 * (1.f/CDIM);
            float ra = rsqrtf(s2 * (1.f/CDIM) - ma*ma + EPS);
            float ms = t1 * (1.f/CDIM);
            float rs = rsqrtf(t2 * (1.f/CDIM) - ms*ms + EPS);
            float* pa = sA + lrow * SA_STRIDE + lane * 4;
            float* ps = sS + lrow * SA_STRIDE + lane * 4;
            pa[0] = (av.x - ma) * ra; pa[1] = (av.y - ma) * ra;
            pa[2] = (av.z - ma) * ra; pa[3] = (av.w - ma) * ra;
            ps[0] = (sv.x - ms) * rs * sc.x; ps[1] = (sv.y - ms) * rs * sc.y;
            ps[2] = (sv.z - ms) * rs * sc.z; ps[3] = (sv.w - ms) * rs * sc.w;
        }
    }
    __syncthreads();

    // ---- phase B: G = sn@Wg, Bm = sn@Wb
    float accG[4][4], accB[4][4];
    gemm_dual<true>(sS, sS, Wg, Wb, sW, tid, accG, accB);

    // ---- epilogue B: aq = sigmoid(G + bg) * lnA + Bm   -> sS
    __syncthreads();   // all warps done reading sS/sA in gemm
    #pragma unroll
    for (int nt = 0; nt < 4; nt++) {
        int col = c0 + nt * 8 + 2 * ctg;
        float bg0 = bg[col], bg1 = bg[col + 1];
        #pragma unroll
        for (int i = 0; i < 2; i++) {
            int lrow = r0 + gid + i * 8;
            float* pr = sS + lrow * SA_STRIDE + col;
            const float* pl = sA + lrow * SA_STRIDE + col;
            pr[0] = sigmoidf_(accG[nt][2*i]   + bg0) * pl[0] + accB[nt][2*i];
            pr[1] = sigmoidf_(accG[nt][2*i+1] + bg1) * pl[1] + accB[nt][2*i+1];
        }
    }
    // gemm_dual's internal leading __syncthreads orders these writes

    // ---- phase C: o1 = aq@W1, o2 = aq@W2
    float acc1[4][4], acc2[4][4];
    gemm_dual<true>(sS, sS, W1, W2, sW, tid, acc1, acc2);

    #pragma unroll
    for (int nt = 0; nt < 4; nt++) {
        int col = c0 + nt * 8 + 2 * ctg;
        float bb0 = 0.f, bb1 = 0.f;
        if (SIDE == 0) { bb0 = b1[col]; bb1 = b1[col + 1]; }
        #pragma unroll
        for (int i = 0; i < 2; i++) {
            int grow = row0 + r0 + gid + i * 8;
            size_t idx = (size_t)grow * CDIM + col;
            if (SIDE == 0) {
                out1[idx]     = (acc1[nt][2*i]   + bb0) * QK_SCALE;
                out1[idx + 1] = (acc1[nt][2*i+1] + bb1) * QK_SCALE;
                out2[idx]     = sigmoidf_(acc2[nt][2*i]);
                out2[idx + 1] = sigmoidf_(acc2[nt][2*i+1]);
            } else {
                out1[idx]     = acc1[nt][2*i];
                out1[idx + 1] = acc1[nt][2*i+1];
                out2[idx]     = acc2[nt][2*i];
                out2[idx + 1] = acc2[nt][2*i+1];
            }
        }
    }
}

// ------------------------------ final kernel -------------------------------
// out = sigmoid(s_q@Ws + bs) * (og@Wo)
__global__ __launch_bounds__(256) void final_kernel(
    const float* __restrict__ og, const float* __restrict__ sq,
    const float* __restrict__ Wo, const float* __restrict__ Ws,
    const float* __restrict__ bs, float* __restrict__ out) {

    extern __shared__ float smem[];
    float* sA1 = smem;                     // og tile
    float* sA2 = smem + 32 * SA_STRIDE;    // s_q tile
    float* sW  = smem + 2 * 32 * SA_STRIDE;

    const int tid = threadIdx.x;
    const int lane = tid & 31, warp = tid >> 5;
    const int gid = lane >> 2, ctg = lane & 3;
    const int r0 = (warp & 1) * 16;
    const int c0 = (warp >> 1) * 32;
    const int row0 = blockIdx.x * 32;

    #pragma unroll
    for (int i = 0; i < 4; i++) {
        int e = tid + i * 256;
        int r = e >> 5, c4 = e & 31;
        cp16(sA1 + r * SA_STRIDE + c4 * 4, og + (size_t)(row0 + r) * CDIM + c4 * 4);
        cp16(sA2 + r * SA_STRIDE + c4 * 4, sq + (size_t)(row0 + r) * CDIM + c4 * 4);
    }
    asm volatile("cp.async.commit_group;\ncp.async.wait_group 0;" ::: "memory");
    // gemm_dual's internal leading __syncthreads orders these

    float acc1[4][4], acc2[4][4];
    gemm_dual<false>(sA1, sA2, Wo, Ws, sW, tid, acc1, acc2);

    #pragma unroll
    for (int nt = 0; nt < 4; nt++) {
        int col = c0 + nt * 8 + 2 * ctg;
        float b0 = bs[col], b1 = bs[col + 1];
        #pragma unroll
        for (int i = 0; i < 2; i++) {
            int grow = row0 + r0 + gid + i * 8;
            size_t idx = (size_t)grow * CDIM + col;
            out[idx]     = sigmoidf_(acc2[nt][2*i]   + b0) * acc1[nt][2*i];
            out[idx + 1] = sigmoidf_(acc2[nt][2*i+1] + b1) * acc1[nt][2*i+1];
        }
    }
}

// --------------------------- attention kernel ------------------------------
#define K_STRIDE 132
#define V_STRIDE 136
#define P_STRIDE 68
#define SMEM_FLOATS (64 * K_STRIDE + 64 * V_STRIDE + NHEAD * 32 * P_STRIDE)
#define SMEM_BYTES  (SMEM_FLOATS * 4)

__global__ __launch_bounds__(256, 1) void attn_kernel(
    const float* __restrict__ z,
    const float* __restrict__ gq, const float* __restrict__ gk,
    const float* __restrict__ gv, const float* __restrict__ gg,
    float* __restrict__ og) {

    extern __shared__ float smem[];
    float* Ksm = smem;
    float* Vsm = smem + 64 * K_STRIDE;
    float* Psm = Vsm + 64 * V_STRIDE;

    const int tid  = threadIdx.x;
    const int lane = tid & 31, warp = tid >> 5;
    const int h = warp >> 1, qh = warp & 1;
    const int gid = lane >> 2, ctg = lane & 3;
    const int qg0 = blockIdx.x * 32;

    const float csum0 = c_bias[64], csum1 = c_bias[65];
    const float csum2 = c_bias[66], csum3 = c_bias[67];

    // Q fragments (A of m16n8k8 tf32), q is pre-scaled by 1/sqrt(c)
    uint32_t qa[4][4];
    {
        int r0 = qg0 + qh * 16 + gid;
        const float* qp = gq + (size_t)r0 * CDIM + h * HDIM + ctg;
        #pragma unroll
        for (int ks = 0; ks < 4; ks++) {
            qa[ks][0] = f2tf32(qp[ks*8]);
            qa[ks][1] = f2tf32(qp[8*CDIM + ks*8]);
            qa[ks][2] = f2tf32(qp[ks*8 + 4]);
            qa[ks][3] = f2tf32(qp[8*CDIM + ks*8 + 4]);
        }
    }

    float O[4][4];
    #pragma unroll
    for (int i = 0; i < 4; i++) { O[i][0]=O[i][1]=O[i][2]=O[i][3]=0.f; }
    float m1 = -1e30f, m2 = -1e30f, l1 = 0.f, l2 = 0.f;

    const int kk0 = tid & 63;   // key within tile for bias phase
    const int qq0 = tid >> 6;   // base q row (0..3) for bias phase

    // preload z regs for (tile 0, qi 0) — carried across iterations
    float4 zb0, zb1, zb2, zb3;
    {
        const float4* zp = (const float4*)(z + ((size_t)(qg0 + qq0) * NSEQ + kk0) * CZ);
        zb0 = zp[0]; zb1 = zp[1]; zb2 = zp[2]; zb3 = zp[3];
    }

    for (int kb = 0; kb < NSEQ; kb += 64) {
        __syncthreads();   // previous tile fully consumed

        // ---- prefetch K/V tile into smem (cp.async; overlaps with z stream)
        #pragma unroll
        for (int i = 0; i < 8; i++) {
            int e = tid + i * 256;
            int r = e >> 5, c4 = e & 31;
            cp16(Ksm + r * K_STRIDE + c4 * 4, gk + (size_t)(kb + r) * CDIM + c4 * 4);
        }
        #pragma unroll
        for (int i = 0; i < 8; i++) {
            int e = tid + i * 256;
            int r = e >> 5, c4 = e & 31;
            cp16(Vsm + r * V_STRIDE + c4 * 4, gv + (size_t)(kb + r) * CDIM + c4 * 4);
        }
        asm volatile("cp.async.commit_group;" ::: "memory");

        // ---- bias phase: LN(z)@Wbias fused (premultiplied weights)
        {
            int kb_next = (kb + 64 < NSEQ) ? (kb + 64) : 0;  // wrap keeps addr valid
            #pragma unroll
            for (int qi = 0; qi < 8; qi++) {
                float4 zc[4] = { zb0, zb1, zb2, zb3 };
                // prefetch next (qi+1 in this tile, or qi=0 of next tile)
                {
                    const float4* zn;
                    if (qi < 7)
                        zn = (const float4*)(z + ((size_t)(qg0 + qq0 + (qi+1)*4) * NSEQ + kb + kk0) * CZ);
                    else
                        zn = (const float4*)(z + ((size_t)(qg0 + qq0) * NSEQ + kb_next + kk0) * CZ);
                    zb0 = zn[0]; zb1 = zn[1]; zb2 = zn[2]; zb3 = zn[3];
                }
                float s1 = 0.f, s2 = 0.f, d0 = 0.f, d1 = 0.f, d2 = 0.f, d3 = 0.f;
                #pragma unroll
                for (int j = 0; j < 4; j++) {
                    float4 v = zc[j];
                    int cb = j * 4;
                    s1 += v.x + v.y + v.z + v.w;
                    s2 += v.x*v.x + v.y*v.y + v.z*v.z + v.w*v.w;
                    d0 += v.x*c_bias[(cb+0)*4+0]; d1 += v.x*c_bias[(cb+0)*4+1];
                    d2 += v.x*c_bias[(cb+0)*4+2]; d3 += v.x*c_bias[(cb+0)*4+3];
                    d0 += v.y*c_bias[(cb+1)*4+0]; d1 += v.y*c_bias[(cb+1)*4+1];
                    d2 += v.y*c_bias[(cb+1)*4+2]; d3 += v.y*c_bias[(cb+1)*4+3];
                    d0 += v.z*c_bias[(cb+2)*4+0]; d1 += v.z*c_bias[(cb+2)*4+1];
                    d2 += v.z*c_bias[(cb+2)*4+2]; d3 += v.z*c_bias[(cb+2)*4+3];
                    d0 += v.w*c_bias[(cb+3)*4+0]; d1 += v.w*c_bias[(cb+3)*4+1];
                    d2 += v.w*c_bias[(cb+3)*4+2]; d3 += v.w*c_bias[(cb+3)*4+3];
                }
                float mm = s1 * (1.f/CZ);
                float var = s2 * (1.f/CZ) - mm * mm;
                float rstd = rsqrtf(var + EPS);
                int q = qq0 + qi * 4;
                float* pb = Psm + q * P_STRIDE + kk0;
                pb[0 * 32 * P_STRIDE] = (d0 - mm * csum0) * rstd;
                pb[1 * 32 * P_STRIDE] = (d1 - mm * csum1) * rstd;
                pb[2 * 32 * P_STRIDE] = (d2 - mm * csum2) * rstd;
                pb[3 * 32 * P_STRIDE] = (d3 - mm * csum3) * rstd;
            }
        }
        asm volatile("cp.async.wait_group 0;" ::: "memory");
        __syncthreads();   // bias + K/V visible to everyone

        // ---- QK^T (tf32 mma): S[16q x 64k] per warp
        float S[8][4];
        #pragma unroll
        for (int nt = 0; nt < 8; nt++) {
            S[nt][0] = S[nt][1] = S[nt][2] = S[nt][3] = 0.f;
            const float* kp = Ksm + (nt * 8 + gid) * K_STRIDE + h * HDIM + ctg;
            #pragma unroll
            for (int ks = 0; ks < 4; ks++) {
                uint32_t b[2];
                b[0] = __float_as_uint(kp[ks * 8]);
                b[1] = __float_as_uint(kp[ks * 8 + 4]);
                mma_tf32(S[nt], qa[ks], b);
            }
        }

        // ---- bias add + online softmax
        float* pwarp = Psm + h * 32 * P_STRIDE + (qh * 16) * P_STRIDE;
        float mx1 = -1e30f, mx2 = -1e30f;
        #pragma unroll
        for (int nt = 0; nt < 8; nt++) {
            int col = nt * 8 + 2 * ctg;
            S[nt][0] += pwarp[gid * P_STRIDE + col];
            S[nt][1] += pwarp[gid * P_STRIDE + col + 1];
            S[nt][2] += pwarp[(gid + 8) * P_STRIDE + col];
            S[nt][3] += pwarp[(gid + 8) * P_STRIDE + col + 1];
            mx1 = fmaxf(mx1, fmaxf(S[nt][0], S[nt][1]));
            mx2 = fmaxf(mx2, fmaxf(S[nt][2], S[nt][3]));
        }
        mx1 = fmaxf(mx1, __shfl_xor_sync(~0u, mx1, 1));
        mx1 = fmaxf(mx1, __shfl_xor_sync(~0u, mx1, 2));
        mx2 = fmaxf(mx2, __shfl_xor_sync(~0u, mx2, 1));
        mx2 = fmaxf(mx2, __shfl_xor_sync(~0u, mx2, 2));
        float mn1 = fmaxf(m1, mx1), mn2 = fmaxf(m2, mx2);
        float al1 = __expf(m1 - mn1), al2 = __expf(m2 - mn2);
        float rs1 = 0.f, rs2 = 0.f;
        #pragma unroll
        for (int nt = 0; nt < 8; nt++) {
            float p0 = __expf(S[nt][0] - mn1);
            float p1 = __expf(S[nt][1] - mn1);
            float p2 = __expf(S[nt][2] - mn2);
            float p3 = __expf(S[nt][3] - mn2);
            rs1 += p0 + p1; rs2 += p2 + p3;
            int col = nt * 8 + 2 * ctg;
            pwarp[gid * P_STRIDE + col]           = __uint_as_float(f2tf32(p0));
            pwarp[gid * P_STRIDE + col + 1]       = __uint_as_float(f2tf32(p1));
            pwarp[(gid + 8) * P_STRIDE + col]     = __uint_as_float(f2tf32(p2));
            pwarp[(gid + 8) * P_STRIDE + col + 1] = __uint_as_float(f2tf32(p3));
        }
        rs1 += __shfl_xor_sync(~0u, rs1, 1); rs1 += __shfl_xor_sync(~0u, rs1, 2);
        rs2 += __shfl_xor_sync(~0u, rs2, 1); rs2 += __shfl_xor_sync(~0u, rs2, 2);
        l1 = l1 * al1 + rs1; l2 = l2 * al2 + rs2;
        m1 = mn1; m2 = mn2;
        #pragma unroll
        for (int on = 0; on < 4; on++) {
            O[on][0] *= al1; O[on][1] *= al1; O[on][2] *= al2; O[on][3] *= al2;
        }
        __syncwarp();

        // ---- PV (tf32 mma): O[16q x 32c] += P[16q x 64k] @ V[64k x 32c]
        #pragma unroll
        for (int on = 0; on < 4; on++) {
            #pragma unroll
            for (int ks = 0; ks < 8; ks++) {
                uint32_t a[4], b[2];
                const float* pp = pwarp + gid * P_STRIDE + ks * 8 + ctg;
                a[0] = __float_as_uint(pp[0]);
                a[1] = __float_as_uint(pp[8 * P_STRIDE]);
                a[2] = __float_as_uint(pp[4]);
                a[3] = __float_as_uint(pp[8 * P_STRIDE + 4]);
                const float* vp = Vsm + (ks * 8 + ctg) * V_STRIDE + h * HDIM + on * 8 + gid;
                b[0] = __float_as_uint(vp[0]);
                b[1] = __float_as_uint(vp[4 * V_STRIDE]);
                mma_tf32(O[on], a, b);
            }
        }
    }

    // ---- epilogue: normalize, gate, store
    float r1 = 1.f / l1, r2 = 1.f / l2;
    int row1 = qg0 + qh * 16 + gid, row2 = row1 + 8;
    #pragma unroll
    for (int on = 0; on < 4; on++) {
        int col = h * HDIM + on * 8 + 2 * ctg;
        size_t i1 = (size_t)row1 * CDIM + col;
        size_t i2 = (size_t)row2 * CDIM + col;
        og[i1]     = O[on][0] * r1 * gg[i1];
        og[i1 + 1] = O[on][1] * r1 * gg[i1 + 1];
        og[i2]     = O[on][2] * r2 * gg[i2];
        og[i2 + 1] = O[on][3] * r2 * gg[i2 + 1];
    }
}

// ------------------------------ launch -------------------------------------
extern "C" void kernel_launch(void* const* d_in, const int* in_sizes, int n_in,
                              void* d_out, int out_size) {
    const float* a_q      = (const float*)d_in[0];
    const float* a_k      = (const float*)d_in[1];
    const float* z        = (const float*)d_in[2];
    const float* s_q      = (const float*)d_in[3];
    const float* s_k      = (const float*)d_in[4];
    const float* Wg_q     = (const float*)d_in[5];
    const float* bg_q     = (const float*)d_in[6];
    const float* Wb_q     = (const float*)d_in[7];
    const float* sscale_q = (const float*)d_in[8];
    const float* Wg_k     = (const float*)d_in[9];
    const float* bg_k     = (const float*)d_in[10];
    const float* Wb_k     = (const float*)d_in[11];
    const float* sscale_k = (const float*)d_in[12];
    const float* lnz      = (const float*)d_in[13];
    const float* Wq       = (const float*)d_in[14];
    const float* bq       = (const float*)d_in[15];
    const float* Wk       = (const float*)d_in[16];
    const float* Wv       = (const float*)d_in[17];
    const float* Wbias    = (const float*)d_in[18];
    const float* Wgate    = (const float*)d_in[19];
    const float* Wo       = (const float*)d_in[20];
    const float* Ws       = (const float*)d_in[21];
    const float* bs       = (const float*)d_in[22];

    float* scratch = nullptr;
    cudaGetSymbolAddress((void**)&scratch, g_scratch);
    const size_t SL = (size_t)NSEQ * CDIM;
    float* qbuf  = scratch + 0 * SL;
    float* gbuf  = scratch + 1 * SL;
    float* kbuf  = scratch + 2 * SL;
    float* vbuf  = scratch + 3 * SL;
    float* ogbuf = scratch + 4 * SL;
    float* biasw = scratch + 5 * SL;

    // premultiplied bias weights -> constant bank
    init_bias<<<1, 96>>>(lnz, Wbias, biasw);
    cudaMemcpyToSymbolAsync(c_bias, biasw, (CZ * NHEAD + NHEAD) * sizeof(float), 0,
                            cudaMemcpyDeviceToDevice, 0);

    cudaFuncSetAttribute(side_kernel<0>, cudaFuncAttributeMaxDynamicSharedMemorySize,
                         SMEM_SIDE_BYTES);
    cudaFuncSetAttribute(side_kernel<1>, cudaFuncAttributeMaxDynamicSharedMemorySize,
                         SMEM_SIDE_BYTES);
    cudaFuncSetAttribute(final_kernel, cudaFuncAttributeMaxDynamicSharedMemorySize,
                         SMEM_SIDE_BYTES);
    cudaFuncSetAttribute(attn_kernel, cudaFuncAttributeMaxDynamicSharedMemorySize,
                         SMEM_BYTES);

    side_kernel<0><<<NSEQ / 32, 256, SMEM_SIDE_BYTES>>>(
        a_q, s_q, sscale_q, Wg_q, bg_q, Wb_q, Wq, bq, Wgate, qbuf, gbuf);
    side_kernel<1><<<NSEQ / 32, 256, SMEM_SIDE_BYTES>>>(
        a_k, s_k, sscale_k, Wg_k, bg_k, Wb_k, Wk, nullptr, Wv, kbuf, vbuf);

    attn_kernel<<<NSEQ / 32, 256, SMEM_BYTES>>>(z, qbuf, kbuf, vbuf, gbuf, ogbuf);

    final_kernel<<<NSEQ / 32, 256, SMEM_SIDE_BYTES>>>(
        ogbuf, s_q, Wo, Ws, bs, (float*)d_out);
}

// round 5
// speedup vs baseline: 1.1005x; 1.0021x over previous
#include <cuda_runtime.h>
#include <cuda_bf16.h>
#include <cstdint>
#include <cstdio>

// ---------------------------------------------------------------------------
// AtomAttentionPairBias: B=1, Nq=Nk=4096, C=128, H=4, c=32, CZ=16  (all fp32)
//
//   1. init_bias: premultiply lnz*Wbias -> constant bank
//   2. side_kernel<Q/K>: LN -> AdaLN -> {q,gate} / {k,v}; all GEMMs via
//      split-tf32 (hi/lo, 3 mma) tensor-core math, chained in-block via smem
//   3. attn_kernel: flash attention, z-bias fused (z streamed ONCE),
//      tf32 mma for QK^T and PV, cross-tile z prefetch
//   4. final_kernel: out = sigmoid(s_q@Ws+bs) * (og@Wo), split-tf32
// ---------------------------------------------------------------------------

#define NSEQ 4096
#define CDIM 128
#define NHEAD 4
#define HDIM 32
#define CZ 16
#define EPS 1e-5f
#define QK_SCALE 0.17677669529663687f   // 1/sqrt(32)

__device__ float g_scratch[6u * NSEQ * CDIM];

// c_bias[0..63]  = lnz[c] * Wbias[c][h]  (row-major [cz][h])
// c_bias[64..67] = per-head column sums of the above
__constant__ float c_bias[CZ * NHEAD + NHEAD];

__device__ __forceinline__ float sigmoidf_(float x) { return 1.f / (1.f + __expf(-x)); }

__device__ __forceinline__ uint32_t f2tf32(float x) {
    uint32_t y; asm("cvt.rna.tf32.f32 %0, %1;" : "=r"(y) : "f"(x)); return y;
}
__device__ __forceinline__ void mma_tf32(float* d, const uint32_t* a, const uint32_t* b) {
    asm volatile("mma.sync.aligned.m16n8k8.row.col.f32.tf32.tf32.f32 "
                 "{%0,%1,%2,%3}, {%4,%5,%6,%7}, {%8,%9}, {%0,%1,%2,%3};"
                 : "+f"(d[0]), "+f"(d[1]), "+f"(d[2]), "+f"(d[3])
                 : "r"(a[0]), "r"(a[1]), "r"(a[2]), "r"(a[3]), "r"(b[0]), "r"(b[1]));
}
__device__ __forceinline__ void cp16(float* dst, const float* src) {
    uint32_t d = (uint32_t)__cvta_generic_to_shared(dst);
    asm volatile("cp.async.cg.shared.global [%0], [%1], 16;" :: "r"(d), "l"(src));
}

// ------------------------------ init_bias ----------------------------------
__global__ void init_bias(const float* __restrict__ lnz, const float* __restrict__ wb,
                          float* __restrict__ out) {
    int t = threadIdx.x;
    if (t < 64) out[t] = lnz[t >> 2] * wb[t];
    if (t >= 64 && t < 68) {
        int h = t - 64;
        float s = 0.f;
        for (int c = 0; c < CZ; c++) s += lnz[c] * wb[c * 4 + h];
        out[t] = s;
    }
}

// ------------------- split-tf32 dual GEMM tile helper -----------------------
// Block computes [32 rows x 128 cols] for TWO GEMMs:
//   acc1 = A1[32x128] @ W1[128x128],  acc2 = A2[32x128] @ W2[128x128]
// A tiles live in smem with row stride 132 (fp32). W streamed via smem chunks
// of 64 k-rows, stride 136. Split-tf32: x = hi + lo; D += hi*Bhi + hi*Blo + lo*Bhi.
// Warp w: rows r0=(w&1)*16, cols c0=(w>>1)*32. Accumulator layout (m16n8):
//   acc[nt][0]=D[gid][2ctg] acc[nt][1]=D[gid][2ctg+1] acc[nt][2..3]=rows gid+8.
#define SA_STRIDE 132
#define SW_STRIDE 136

template<bool SAME_A>
__device__ __forceinline__ void gemm_dual(
    const float* __restrict__ sA1, const float* __restrict__ sA2,
    const float* __restrict__ gW1, const float* __restrict__ gW2,
    float* sW, int tid, float acc1[4][4], float acc2[4][4]) {

    const int lane = tid & 31, warp = tid >> 5;
    const int gid = lane >> 2, ctg = lane & 3;
    const int r0 = (warp & 1) * 16;
    const int c0 = (warp >> 1) * 32;

    #pragma unroll
    for (int nt = 0; nt < 4; nt++)
        #pragma unroll
        for (int j = 0; j < 4; j++) { acc1[nt][j] = 0.f; acc2[nt][j] = 0.f; }

    for (int kc = 0; kc < CDIM; kc += 64) {
        __syncthreads();   // protect sW from previous chunk's readers
        #pragma unroll
        for (int i = 0; i < 8; i++) {
            int e = tid + i * 256;
            int r = e >> 5, c4 = e & 31;
            cp16(sW + r * SW_STRIDE + c4 * 4, gW1 + (size_t)(kc + r) * CDIM + c4 * 4);
            cp16(sW + 64 * SW_STRIDE + r * SW_STRIDE + c4 * 4,
                 gW2 + (size_t)(kc + r) * CDIM + c4 * 4);
        }
        asm volatile("cp.async.commit_group;\ncp.async.wait_group 0;" ::: "memory");
        __syncthreads();

        #pragma unroll
        for (int ks = 0; ks < 8; ks++) {
            int kg = kc + ks * 8;
            uint32_t a1h[4], a1l[4], a2h[4], a2l[4];
            {
                const float* ap = sA1 + (r0 + gid) * SA_STRIDE + kg + ctg;
                float x;
                x = ap[0];               a1h[0] = f2tf32(x); a1l[0] = f2tf32(x - __uint_as_float(a1h[0]));
                x = ap[8 * SA_STRIDE];   a1h[1] = f2tf32(x); a1l[1] = f2tf32(x - __uint_as_float(a1h[1]));
                x = ap[4];               a1h[2] = f2tf32(x); a1l[2] = f2tf32(x - __uint_as_float(a1h[2]));
                x = ap[8 * SA_STRIDE+4]; a1h[3] = f2tf32(x); a1l[3] = f2tf32(x - __uint_as_float(a1h[3]));
            }
            if (!SAME_A) {
                const float* ap = sA2 + (r0 + gid) * SA_STRIDE + kg + ctg;
                float x;
                x = ap[0];               a2h[0] = f2tf32(x); a2l[0] = f2tf32(x - __uint_as_float(a2h[0]));
                x = ap[8 * SA_STRIDE];   a2h[1] = f2tf32(x); a2l[1] = f2tf32(x - __uint_as_float(a2h[1]));
                x = ap[4];               a2h[2] = f2tf32(x); a2l[2] = f2tf32(x - __uint_as_float(a2h[2]));
                x = ap[8 * SA_STRIDE+4]; a2h[3] = f2tf32(x); a2l[3] = f2tf32(x - __uint_as_float(a2h[3]));
            }
            #pragma unroll
            for (int nt = 0; nt < 4; nt++) {
                const float* bp = sW + (ks * 8 + ctg) * SW_STRIDE + c0 + nt * 8 + gid;
                uint32_t bh[2], bl[2];
                float b0 = bp[0], b1 = bp[4 * SW_STRIDE];
                bh[0] = f2tf32(b0); bl[0] = f2tf32(b0 - __uint_as_float(bh[0]));
                bh[1] = f2tf32(b1); bl[1] = f2tf32(b1 - __uint_as_float(bh[1]));
                mma_tf32(acc1[nt], a1h, bh);
                mma_tf32(acc1[nt], a1h, bl);
                mma_tf32(acc1[nt], a1l, bh);
                const float* bp2 = bp + 64 * SW_STRIDE;
                b0 = bp2[0]; b1 = bp2[4 * SW_STRIDE];
                bh[0] = f2tf32(b0); bl[0] = f2tf32(b0 - __uint_as_float(bh[0]));
                bh[1] = f2tf32(b1); bl[1] = f2tf32(b1 - __uint_as_float(bh[1]));
                if (SAME_A) {
                    mma_tf32(acc2[nt], a1h, bh);
                    mma_tf32(acc2[nt], a1h, bl);
                    mma_tf32(acc2[nt], a1l, bh);
                } else {
                    mma_tf32(acc2[nt], a2h, bh);
                    mma_tf32(acc2[nt], a2h, bl);
                    mma_tf32(acc2[nt], a2l, bh);
                }
            }
        }
    }
}

#define SMEM_SIDE_FLOATS (2 * 32 * SA_STRIDE + 2 * 64 * SW_STRIDE)
#define SMEM_SIDE_BYTES  (SMEM_SIDE_FLOATS * 4)

// ------------------------------ side kernel --------------------------------
// SIDE=0 (q): out1 = (aq@Wq + bq)*QK_SCALE ; out2 = sigmoid(aq@Wgate)
// SIDE=1 (k): out1 = ak@Wk               ; out2 = ak@Wv
template<int SIDE>
__global__ __launch_bounds__(256) void side_kernel(
    const float* __restrict__ ga, const float* __restrict__ gs,
    const float* __restrict__ sscale,
    const float* __restrict__ Wg, const float* __restrict__ bg,
    const float* __restrict__ Wb,
    const float* __restrict__ W1, const float* __restrict__ b1,
    const float* __restrict__ W2,
    float* __restrict__ out1, float* __restrict__ out2) {

    extern __shared__ float smem[];
    float* sA = smem;                     // LN(a)
    float* sS = smem + 32 * SA_STRIDE;    // LN(s)*sscale, later aq
    float* sW = smem + 2 * 32 * SA_STRIDE;

    const int tid = threadIdx.x;
    const int lane = tid & 31, warp = tid >> 5;
    const int gid = lane >> 2, ctg = lane & 3;
    const int r0 = (warp & 1) * 16;
    const int c0 = (warp >> 1) * 32;
    const int row0 = blockIdx.x * 32;

    // ---- phase A: LN(a), LN(s)*sscale  (warp per row, 4 passes)
    {
        float4 sc = ((const float4*)sscale)[lane];
        #pragma unroll
        for (int rr = 0; rr < 4; rr++) {
            int lrow = rr * 8 + warp;
            const float4* ap = (const float4*)(ga + (size_t)(row0 + lrow) * CDIM);
            const float4* sp = (const float4*)(gs + (size_t)(row0 + lrow) * CDIM);
            float4 av = ap[lane];
            float4 sv = sp[lane];
            float s1 = av.x + av.y + av.z + av.w;
            float s2 = av.x*av.x + av.y*av.y + av.z*av.z + av.w*av.w;
            float t1 = sv.x + sv.y + sv.z + sv.w;
            float t2 = sv.x*sv.x + sv.y*sv.y + sv.z*sv.z + sv.w*sv.w;
            #pragma unroll
            for (int o = 16; o > 0; o >>= 1) {
                s1 += __shfl_xor_sync(~0u, s1, o);
                s2 += __shfl_xor_sync(~0u, s2, o);
                t1 += __shfl_xor_sync(~0u, t1, o);
                t2 += __shfl_xor_sync(~0u, t2, o);
            }
            float ma = s1 * (1.f/CDIM);
            float ra = rsqrtf(s2 * (1.f/CDIM) - ma*ma + EPS);
            float ms = t1 * (1.f/CDIM);
            float rs = rsqrtf(t2 * (1.f/CDIM) - ms*ms + EPS);
            float* pa = sA + lrow * SA_STRIDE + lane * 4;
            float* ps = sS + lrow * SA_STRIDE + lane * 4;
            pa[0] = (av.x - ma) * ra; pa[1] = (av.y - ma) * ra;
            pa[2] = (av.z - ma) * ra; pa[3] = (av.w - ma) * ra;
            ps[0] = (sv.x - ms) * rs * sc.x; ps[1] = (sv.y - ms) * rs * sc.y;
            ps[2] = (sv.z - ms) * rs * sc.z; ps[3] = (sv.w - ms) * rs * sc.w;
        }
    }
    __syncthreads();

    // ---- phase B: G = sn@Wg, Bm = sn@Wb
    float accG[4][4], accB[4][4];
    gemm_dual<true>(sS, sS, Wg, Wb, sW, tid, accG, accB);

    // ---- epilogue B: aq = sigmoid(G + bg) * lnA + Bm   -> sS
    __syncthreads();   // all warps done reading sS/sA in gemm
    #pragma unroll
    for (int nt = 0; nt < 4; nt++) {
        int col = c0 + nt * 8 + 2 * ctg;
        float bg0 = bg[col], bg1 = bg[col + 1];
        #pragma unroll
        for (int i = 0; i < 2; i++) {
            int lrow = r0 + gid + i * 8;
            float* pr = sS + lrow * SA_STRIDE + col;
            const float* pl = sA + lrow * SA_STRIDE + col;
            pr[0] = sigmoidf_(accG[nt][2*i]   + bg0) * pl[0] + accB[nt][2*i];
            pr[1] = sigmoidf_(accG[nt][2*i+1] + bg1) * pl[1] + accB[nt][2*i+1];
        }
    }
    // gemm_dual's internal leading __syncthreads orders these writes

    // ---- phase C: o1 = aq@W1, o2 = aq@W2
    float acc1[4][4], acc2[4][4];
    gemm_dual<true>(sS, sS, W1, W2, sW, tid, acc1, acc2);

    #pragma unroll
    for (int nt = 0; nt < 4; nt++) {
        int col = c0 + nt * 8 + 2 * ctg;
        float bb0 = 0.f, bb1 = 0.f;
        if (SIDE == 0) { bb0 = b1[col]; bb1 = b1[col + 1]; }
        #pragma unroll
        for (int i = 0; i < 2; i++) {
            int grow = row0 + r0 + gid + i * 8;
            size_t idx = (size_t)grow * CDIM + col;
            if (SIDE == 0) {
                out1[idx]     = (acc1[nt][2*i]   + bb0) * QK_SCALE;
                out1[idx + 1] = (acc1[nt][2*i+1] + bb1) * QK_SCALE;
                out2[idx]     = sigmoidf_(acc2[nt][2*i]);
                out2[idx + 1] = sigmoidf_(acc2[nt][2*i+1]);
            } else {
                out1[idx]     = acc1[nt][2*i];
                out1[idx + 1] = acc1[nt][2*i+1];
                out2[idx]     = acc2[nt][2*i];
                out2[idx + 1] = acc2[nt][2*i+1];
            }
        }
    }
}

// ------------------------------ final kernel -------------------------------
// out = sigmoid(s_q@Ws + bs) * (og@Wo)
__global__ __launch_bounds__(256) void final_kernel(
    const float* __restrict__ og, const float* __restrict__ sq,
    const float* __restrict__ Wo, const float* __restrict__ Ws,
    const float* __restrict__ bs, float* __restrict__ out) {

    extern __shared__ float smem[];
    float* sA1 = smem;                     // og tile
    float* sA2 = smem + 32 * SA_STRIDE;    // s_q tile
    float* sW  = smem + 2 * 32 * SA_STRIDE;

    const int tid = threadIdx.x;
    const int lane = tid & 31, warp = tid >> 5;
    const int gid = lane >> 2, ctg = lane & 3;
    const int r0 = (warp & 1) * 16;
    const int c0 = (warp >> 1) * 32;
    const int row0 = blockIdx.x * 32;

    #pragma unroll
    for (int i = 0; i < 4; i++) {
        int e = tid + i * 256;
        int r = e >> 5, c4 = e & 31;
        cp16(sA1 + r * SA_STRIDE + c4 * 4, og + (size_t)(row0 + r) * CDIM + c4 * 4);
        cp16(sA2 + r * SA_STRIDE + c4 * 4, sq + (size_t)(row0 + r) * CDIM + c4 * 4);
    }
    asm volatile("cp.async.commit_group;\ncp.async.wait_group 0;" ::: "memory");
    // gemm_dual's internal leading __syncthreads orders these

    float acc1[4][4], acc2[4][4];
    gemm_dual<false>(sA1, sA2, Wo, Ws, sW, tid, acc1, acc2);

    #pragma unroll
    for (int nt = 0; nt < 4; nt++) {
        int col = c0 + nt * 8 + 2 * ctg;
        float b0 = bs[col], b1 = bs[col + 1];
        #pragma unroll
        for (int i = 0; i < 2; i++) {
            int grow = row0 + r0 + gid + i * 8;
            size_t idx = (size_t)grow * CDIM + col;
            out[idx]     = sigmoidf_(acc2[nt][2*i]   + b0) * acc1[nt][2*i];
            out[idx + 1] = sigmoidf_(acc2[nt][2*i+1] + b1) * acc1[nt][2*i+1];
        }
    }
}

// --------------------------- attention kernel ------------------------------
#define K_STRIDE 132
#define V_STRIDE 136
#define P_STRIDE 68
#define SMEM_FLOATS (64 * K_STRIDE + 64 * V_STRIDE + NHEAD * 32 * P_STRIDE)
#define SMEM_BYTES  (SMEM_FLOATS * 4)

__global__ __launch_bounds__(256, 1) void attn_kernel(
    const float* __restrict__ z,
    const float* __restrict__ gq, const float* __restrict__ gk,
    const float* __restrict__ gv, const float* __restrict__ gg,
    float* __restrict__ og) {

    extern __shared__ float smem[];
    float* Ksm = smem;
    float* Vsm = smem + 64 * K_STRIDE;
    float* Psm = Vsm + 64 * V_STRIDE;

    const int tid  = threadIdx.x;
    const int lane = tid & 31, warp = tid >> 5;
    const int h = warp >> 1, qh = warp & 1;
    const int gid = lane >> 2, ctg = lane & 3;
    const int qg0 = blockIdx.x * 32;

    const float csum0 = c_bias[64], csum1 = c_bias[65];
    const float csum2 = c_bias[66], csum3 = c_bias[67];

    // Q fragments (A of m16n8k8 tf32), q is pre-scaled by 1/sqrt(c)
    uint32_t qa[4][4];
    {
        int r0 = qg0 + qh * 16 + gid;
        const float* qp = gq + (size_t)r0 * CDIM + h * HDIM + ctg;
        #pragma unroll
        for (int ks = 0; ks < 4; ks++) {
            qa[ks][0] = f2tf32(qp[ks*8]);
            qa[ks][1] = f2tf32(qp[8*CDIM + ks*8]);
            qa[ks][2] = f2tf32(qp[ks*8 + 4]);
            qa[ks][3] = f2tf32(qp[8*CDIM + ks*8 + 4]);
        }
    }

    float O[4][4];
    #pragma unroll
    for (int i = 0; i < 4; i++) { O[i][0]=O[i][1]=O[i][2]=O[i][3]=0.f; }
    float m1 = -1e30f, m2 = -1e30f, l1 = 0.f, l2 = 0.f;

    const int kk0 = tid & 63;   // key within tile for bias phase
    const int qq0 = tid >> 6;   // base q row (0..3) for bias phase

    // preload z regs for (tile 0, qi 0) — carried across iterations
    float4 zb0, zb1, zb2, zb3;
    {
        const float4* zp = (const float4*)(z + ((size_t)(qg0 + qq0) * NSEQ + kk0) * CZ);
        zb0 = zp[0]; zb1 = zp[1]; zb2 = zp[2]; zb3 = zp[3];
    }

    for (int kb = 0; kb < NSEQ; kb += 64) {
        __syncthreads();   // previous tile fully consumed

        // ---- prefetch K/V tile into smem (cp.async; overlaps with z stream)
        #pragma unroll
        for (int i = 0; i < 8; i++) {
            int e = tid + i * 256;
            int r = e >> 5, c4 = e & 31;
            cp16(Ksm + r * K_STRIDE + c4 * 4, gk + (size_t)(kb + r) * CDIM + c4 * 4);
        }
        #pragma unroll
        for (int i = 0; i < 8; i++) {
            int e = tid + i * 256;
            int r = e >> 5, c4 = e & 31;
            cp16(Vsm + r * V_STRIDE + c4 * 4, gv + (size_t)(kb + r) * CDIM + c4 * 4);
        }
        asm volatile("cp.async.commit_group;" ::: "memory");

        // ---- bias phase: LN(z)@Wbias fused (premultiplied weights)
        {
            int kb_next = (kb + 64 < NSEQ) ? (kb + 64) : 0;  // wrap keeps addr valid
            #pragma unroll
            for (int qi = 0; qi < 8; qi++) {
                float4 zc[4] = { zb0, zb1, zb2, zb3 };
                // prefetch next (qi+1 in this tile, or qi=0 of next tile)
                {
                    const float4* zn;
                    if (qi < 7)
                        zn = (const float4*)(z + ((size_t)(qg0 + qq0 + (qi+1)*4) * NSEQ + kb + kk0) * CZ);
                    else
                        zn = (const float4*)(z + ((size_t)(qg0 + qq0) * NSEQ + kb_next + kk0) * CZ);
                    zb0 = zn[0]; zb1 = zn[1]; zb2 = zn[2]; zb3 = zn[3];
                }
                float s1 = 0.f, s2 = 0.f, d0 = 0.f, d1 = 0.f, d2 = 0.f, d3 = 0.f;
                #pragma unroll
                for (int j = 0; j < 4; j++) {
                    float4 v = zc[j];
                    int cb = j * 4;
                    s1 += v.x + v.y + v.z + v.w;
                    s2 += v.x*v.x + v.y*v.y + v.z*v.z + v.w*v.w;
                    d0 += v.x*c_bias[(cb+0)*4+0]; d1 += v.x*c_bias[(cb+0)*4+1];
                    d2 += v.x*c_bias[(cb+0)*4+2]; d3 += v.x*c_bias[(cb+0)*4+3];
                    d0 += v.y*c_bias[(cb+1)*4+0]; d1 += v.y*c_bias[(cb+1)*4+1];
                    d2 += v.y*c_bias[(cb+1)*4+2]; d3 += v.y*c_bias[(cb+1)*4+3];
                    d0 += v.z*c_bias[(cb+2)*4+0]; d1 += v.z*c_bias[(cb+2)*4+1];
                    d2 += v.z*c_bias[(cb+2)*4+2]; d3 += v.z*c_bias[(cb+2)*4+3];
                    d0 += v.w*c_bias[(cb+3)*4+0]; d1 += v.w*c_bias[(cb+3)*4+1];
                    d2 += v.w*c_bias[(cb+3)*4+2]; d3 += v.w*c_bias[(cb+3)*4+3];
                }
                float mm = s1 * (1.f/CZ);
                float var = s2 * (1.f/CZ) - mm * mm;
                float rstd = rsqrtf(var + EPS);
                int q = qq0 + qi * 4;
                float* pb = Psm + q * P_STRIDE + kk0;
                pb[0 * 32 * P_STRIDE] = (d0 - mm * csum0) * rstd;
                pb[1 * 32 * P_STRIDE] = (d1 - mm * csum1) * rstd;
                pb[2 * 32 * P_STRIDE] = (d2 - mm * csum2) * rstd;
                pb[3 * 32 * P_STRIDE] = (d3 - mm * csum3) * rstd;
            }
        }
        asm volatile("cp.async.wait_group 0;" ::: "memory");
        __syncthreads();   // bias + K/V visible to everyone

        // ---- QK^T (tf32 mma): S[16q x 64k] per warp
        float S[8][4];
        #pragma unroll
        for (int nt = 0; nt < 8; nt++) {
            S[nt][0] = S[nt][1] = S[nt][2] = S[nt][3] = 0.f;
            const float* kp = Ksm + (nt * 8 + gid) * K_STRIDE + h * HDIM + ctg;
            #pragma unroll
            for (int ks = 0; ks < 4; ks++) {
                uint32_t b[2];
                b[0] = __float_as_uint(kp[ks * 8]);
                b[1] = __float_as_uint(kp[ks * 8 + 4]);
                mma_tf32(S[nt], qa[ks], b);
            }
        }

        // ---- bias add + online softmax
        float* pwarp = Psm + h * 32 * P_STRIDE + (qh * 16) * P_STRIDE;
        float mx1 = -1e30f, mx2 = -1e30f;
        #pragma unroll
        for (int nt = 0; nt < 8; nt++) {
            int col = nt * 8 + 2 * ctg;
            S[nt][0] += pwarp[gid * P_STRIDE + col];
            S[nt][1] += pwarp[gid * P_STRIDE + col + 1];
            S[nt][2] += pwarp[(gid + 8) * P_STRIDE + col];
            S[nt][3] += pwarp[(gid + 8) * P_STRIDE + col + 1];
            mx1 = fmaxf(mx1, fmaxf(S[nt][0], S[nt][1]));
            mx2 = fmaxf(mx2, fmaxf(S[nt][2], S[nt][3]));
        }
        mx1 = fmaxf(mx1, __shfl_xor_sync(~0u, mx1, 1));
        mx1 = fmaxf(mx1, __shfl_xor_sync(~0u, mx1, 2));
        mx2 = fmaxf(mx2, __shfl_xor_sync(~0u, mx2, 1));
        mx2 = fmaxf(mx2, __shfl_xor_sync(~0u, mx2, 2));
        float mn1 = fmaxf(m1, mx1), mn2 = fmaxf(m2, mx2);
        float al1 = __expf(m1 - mn1), al2 = __expf(m2 - mn2);
        float rs1 = 0.f, rs2 = 0.f;
        #pragma unroll
        for (int nt = 0; nt < 8; nt++) {
            float p0 = __expf(S[nt][0] - mn1);
            float p1 = __expf(S[nt][1] - mn1);
            float p2 = __expf(S[nt][2] - mn2);
            float p3 = __expf(S[nt][3] - mn2);
            rs1 += p0 + p1; rs2 += p2 + p3;
            int col = nt * 8 + 2 * ctg;
            pwarp[gid * P_STRIDE + col]           = __uint_as_float(f2tf32(p0));
            pwarp[gid * P_STRIDE + col + 1]       = __uint_as_float(f2tf32(p1));
            pwarp[(gid + 8) * P_STRIDE + col]     = __uint_as_float(f2tf32(p2));
            pwarp[(gid + 8) * P_STRIDE + col + 1] = __uint_as_float(f2tf32(p3));
        }
        rs1 += __shfl_xor_sync(~0u, rs1, 1); rs1 += __shfl_xor_sync(~0u, rs1, 2);
        rs2 += __shfl_xor_sync(~0u, rs2, 1); rs2 += __shfl_xor_sync(~0u, rs2, 2);
        l1 = l1 * al1 + rs1; l2 = l2 * al2 + rs2;
        m1 = mn1; m2 = mn2;
        #pragma unroll
        for (int on = 0; on < 4; on++) {
            O[on][0] *= al1; O[on][1] *= al1; O[on][2] *= al2; O[on][3] *= al2;
        }
        __syncwarp();

        // ---- PV (tf32 mma): O[16q x 32c] += P[16q x 64k] @ V[64k x 32c]
        #pragma unroll
        for (int on = 0; on < 4; on++) {
            #pragma unroll
            for (int ks = 0; ks < 8; ks++) {
                uint32_t a[4], b[2];
                const float* pp = pwarp + gid * P_STRIDE + ks * 8 + ctg;
                a[0] = __float_as_uint(pp[0]);
                a[1] = __float_as_uint(pp[8 * P_STRIDE]);
                a[2] = __float_as_uint(pp[4]);
                a[3] = __float_as_uint(pp[8 * P_STRIDE + 4]);
                const float* vp = Vsm + (ks * 8 + ctg) * V_STRIDE + h * HDIM + on * 8 + gid;
                b[0] = __float_as_uint(vp[0]);
                b[1] = __float_as_uint(vp[4 * V_STRIDE]);
                mma_tf32(O[on], a, b);
            }
        }
    }

    // ---- epilogue: normalize, gate, store
    float r1 = 1.f / l1, r2 = 1.f / l2;
    int row1 = qg0 + qh * 16 + gid, row2 = row1 + 8;
    #pragma unroll
    for (int on = 0; on < 4; on++) {
        int col = h * HDIM + on * 8 + 2 * ctg;
        size_t i1 = (size_t)row1 * CDIM + col;
        size_t i2 = (size_t)row2 * CDIM + col;
        og[i1]     = O[on][0] * r1 * gg[i1];
        og[i1 + 1] = O[on][1] * r1 * gg[i1 + 1];
        og[i2]     = O[on][2] * r2 * gg[i2];
        og[i2 + 1] = O[on][3] * r2 * gg[i2 + 1];
    }
}

// ------------------------------ launch -------------------------------------
extern "C" void kernel_launch(void* const* d_in, const int* in_sizes, int n_in,
                              void* d_out, int out_size) {
    const float* a_q      = (const float*)d_in[0];
    const float* a_k      = (const float*)d_in[1];
    const float* z        = (const float*)d_in[2];
    const float* s_q      = (const float*)d_in[3];
    const float* s_k      = (const float*)d_in[4];
    const float* Wg_q     = (const float*)d_in[5];
    const float* bg_q     = (const float*)d_in[6];
    const float* Wb_q     = (const float*)d_in[7];
    const float* sscale_q = (const float*)d_in[8];
    const float* Wg_k     = (const float*)d_in[9];
    const float* bg_k     = (const float*)d_in[10];
    const float* Wb_k     = (const float*)d_in[11];
    const float* sscale_k = (const float*)d_in[12];
    const float* lnz      = (const float*)d_in[13];
    const float* Wq       = (const float*)d_in[14];
    const float* bq       = (const float*)d_in[15];
    const float* Wk       = (const float*)d_in[16];
    const float* Wv       = (const float*)d_in[17];
    const float* Wbias    = (const float*)d_in[18];
    const float* Wgate    = (const float*)d_in[19];
    const float* Wo       = (const float*)d_in[20];
    const float* Ws       = (const float*)d_in[21];
    const float* bs       = (const float*)d_in[22];

    float* scratch = nullptr;
    cudaGetSymbolAddress((void**)&scratch, g_scratch);
    const size_t SL = (size_t)NSEQ * CDIM;
    float* qbuf  = scratch + 0 * SL;
    float* gbuf  = scratch + 1 * SL;
    float* kbuf  = scratch + 2 * SL;
    float* vbuf  = scratch + 3 * SL;
    float* ogbuf = scratch + 4 * SL;
    float* biasw = scratch + 5 * SL;

    // premultiplied bias weights -> constant bank
    init_bias<<<1, 96>>>(lnz, Wbias, biasw);
    cudaMemcpyToSymbolAsync(c_bias, biasw, (CZ * NHEAD + NHEAD) * sizeof(float), 0,
                            cudaMemcpyDeviceToDevice, 0);

    cudaFuncSetAttribute(side_kernel<0>, cudaFuncAttributeMaxDynamicSharedMemorySize,
                         SMEM_SIDE_BYTES);
    cudaFuncSetAttribute(side_kernel<1>, cudaFuncAttributeMaxDynamicSharedMemorySize,
                         SMEM_SIDE_BYTES);
    cudaFuncSetAttribute(final_kernel, cudaFuncAttributeMaxDynamicSharedMemorySize,
                         SMEM_SIDE_BYTES);
    cudaFuncSetAttribute(attn_kernel, cudaFuncAttributeMaxDynamicSharedMemorySize,
                         SMEM_BYTES);

    side_kernel<0><<<NSEQ / 32, 256, SMEM_SIDE_BYTES>>>(
        a_q, s_q, sscale_q, Wg_q, bg_q, Wb_q, Wq, bq, Wgate, qbuf, gbuf);
    side_kernel<1><<<NSEQ / 32, 256, SMEM_SIDE_BYTES>>>(
        a_k, s_k, sscale_k, Wg_k, bg_k, Wb_k, Wk, nullptr, Wv, kbuf, vbuf);

    attn_kernel<<<NSEQ / 32, 256, SMEM_BYTES>>>(z, qbuf, kbuf, vbuf, gbuf, ogbuf);

    final_kernel<<<NSEQ / 32, 256, SMEM_SIDE_BYTES>>>(
        ogbuf, s_q, Wo, Ws, bs, (float*)d_out);
}

// round 6
// speedup vs baseline: 1.1763x; 1.0689x over previous
#include <cuda_runtime.h>
#include <cuda_bf16.h>
#include <cstdint>
#include <cstdio>

// ---------------------------------------------------------------------------
// AtomAttentionPairBias: B=1, Nq=Nk=4096, C=128, H=4, c=32, CZ=16  (all fp32)
//
//   1. init_bias: premultiply lnz*Wbias -> constant bank
//   2. side_kernel<Q/K>: LN -> AdaLN -> {q,gate} / {k,v}; split-tf32 mma
//   3. attn_kernel (WARP-SPECIALIZED): 8 consumer warps do flash attention
//      (tf32 mma QK^T / PV, online softmax); 4 producer warps stream z ONCE
//      and compute the fused LN(z)@Wbias bias for the NEXT tile into a
//      double-buffered Psm. Named-barrier full/empty handshake.
//   4. final_kernel: out = sigmoid(s_q@Ws+bs) * (og@Wo), split-tf32
// ---------------------------------------------------------------------------

#define NSEQ 4096
#define CDIM 128
#define NHEAD 4
#define HDIM 32
#define CZ 16
#define EPS 1e-5f
#define QK_SCALE 0.17677669529663687f   // 1/sqrt(32)

__device__ float g_scratch[6u * NSEQ * CDIM];

// c_bias[0..63]  = lnz[c] * Wbias[c][h]  (row-major [cz][h])
// c_bias[64..67] = per-head column sums of the above
__constant__ float c_bias[CZ * NHEAD + NHEAD];

__device__ __forceinline__ float sigmoidf_(float x) { return 1.f / (1.f + __expf(-x)); }

__device__ __forceinline__ uint32_t f2tf32(float x) {
    uint32_t y; asm("cvt.rna.tf32.f32 %0, %1;" : "=r"(y) : "f"(x)); return y;
}
__device__ __forceinline__ void mma_tf32(float* d, const uint32_t* a, const uint32_t* b) {
    asm volatile("mma.sync.aligned.m16n8k8.row.col.f32.tf32.tf32.f32 "
                 "{%0,%1,%2,%3}, {%4,%5,%6,%7}, {%8,%9}, {%0,%1,%2,%3};"
                 : "+f"(d[0]), "+f"(d[1]), "+f"(d[2]), "+f"(d[3])
                 : "r"(a[0]), "r"(a[1]), "r"(a[2]), "r"(a[3]), "r"(b[0]), "r"(b[1]));
}
__device__ __forceinline__ void cp16(float* dst, const float* src) {
    uint32_t d = (uint32_t)__cvta_generic_to_shared(dst);
    asm volatile("cp.async.cg.shared.global [%0], [%1], 16;" :: "r"(d), "l"(src));
}

// ------------------------------ init_bias ----------------------------------
__global__ void init_bias(const float* __restrict__ lnz, const float* __restrict__ wb,
                          float* __restrict__ out) {
    int t = threadIdx.x;
    if (t < 64) out[t] = lnz[t >> 2] * wb[t];
    if (t >= 64 && t < 68) {
        int h = t - 64;
        float s = 0.f;
        for (int c = 0; c < CZ; c++) s += lnz[c] * wb[c * 4 + h];
        out[t] = s;
    }
}

// ------------------- split-tf32 dual GEMM tile helper -----------------------
#define SA_STRIDE 132
#define SW_STRIDE 136

template<bool SAME_A>
__device__ __forceinline__ void gemm_dual(
    const float* __restrict__ sA1, const float* __restrict__ sA2,
    const float* __restrict__ gW1, const float* __restrict__ gW2,
    float* sW, int tid, float acc1[4][4], float acc2[4][4]) {

    const int lane = tid & 31, warp = tid >> 5;
    const int gid = lane >> 2, ctg = lane & 3;
    const int r0 = (warp & 1) * 16;
    const int c0 = (warp >> 1) * 32;

    #pragma unroll
    for (int nt = 0; nt < 4; nt++)
        #pragma unroll
        for (int j = 0; j < 4; j++) { acc1[nt][j] = 0.f; acc2[nt][j] = 0.f; }

    for (int kc = 0; kc < CDIM; kc += 64) {
        __syncthreads();   // protect sW from previous chunk's readers
        #pragma unroll
        for (int i = 0; i < 8; i++) {
            int e = tid + i * 256;
            int r = e >> 5, c4 = e & 31;
            cp16(sW + r * SW_STRIDE + c4 * 4, gW1 + (size_t)(kc + r) * CDIM + c4 * 4);
            cp16(sW + 64 * SW_STRIDE + r * SW_STRIDE + c4 * 4,
                 gW2 + (size_t)(kc + r) * CDIM + c4 * 4);
        }
        asm volatile("cp.async.commit_group;\ncp.async.wait_group 0;" ::: "memory");
        __syncthreads();

        #pragma unroll
        for (int ks = 0; ks < 8; ks++) {
            int kg = kc + ks * 8;
            uint32_t a1h[4], a1l[4], a2h[4], a2l[4];
            {
                const float* ap = sA1 + (r0 + gid) * SA_STRIDE + kg + ctg;
                float x;
                x = ap[0];               a1h[0] = f2tf32(x); a1l[0] = f2tf32(x - __uint_as_float(a1h[0]));
                x = ap[8 * SA_STRIDE];   a1h[1] = f2tf32(x); a1l[1] = f2tf32(x - __uint_as_float(a1h[1]));
                x = ap[4];               a1h[2] = f2tf32(x); a1l[2] = f2tf32(x - __uint_as_float(a1h[2]));
                x = ap[8 * SA_STRIDE+4]; a1h[3] = f2tf32(x); a1l[3] = f2tf32(x - __uint_as_float(a1h[3]));
            }
            if (!SAME_A) {
                const float* ap = sA2 + (r0 + gid) * SA_STRIDE + kg + ctg;
                float x;
                x = ap[0];               a2h[0] = f2tf32(x); a2l[0] = f2tf32(x - __uint_as_float(a2h[0]));
                x = ap[8 * SA_STRIDE];   a2h[1] = f2tf32(x); a2l[1] = f2tf32(x - __uint_as_float(a2h[1]));
                x = ap[4];               a2h[2] = f2tf32(x); a2l[2] = f2tf32(x - __uint_as_float(a2h[2]));
                x = ap[8 * SA_STRIDE+4]; a2h[3] = f2tf32(x); a2l[3] = f2tf32(x - __uint_as_float(a2h[3]));
            }
            #pragma unroll
            for (int nt = 0; nt < 4; nt++) {
                const float* bp = sW + (ks * 8 + ctg) * SW_STRIDE + c0 + nt * 8 + gid;
                uint32_t bh[2], bl[2];
                float b0 = bp[0], b1 = bp[4 * SW_STRIDE];
                bh[0] = f2tf32(b0); bl[0] = f2tf32(b0 - __uint_as_float(bh[0]));
                bh[1] = f2tf32(b1); bl[1] = f2tf32(b1 - __uint_as_float(bh[1]));
                mma_tf32(acc1[nt], a1h, bh);
                mma_tf32(acc1[nt], a1h, bl);
                mma_tf32(acc1[nt], a1l, bh);
                const float* bp2 = bp + 64 * SW_STRIDE;
                b0 = bp2[0]; b1 = bp2[4 * SW_STRIDE];
                bh[0] = f2tf32(b0); bl[0] = f2tf32(b0 - __uint_as_float(bh[0]));
                bh[1] = f2tf32(b1); bl[1] = f2tf32(b1 - __uint_as_float(bh[1]));
                if (SAME_A) {
                    mma_tf32(acc2[nt], a1h, bh);
                    mma_tf32(acc2[nt], a1h, bl);
                    mma_tf32(acc2[nt], a1l, bh);
                } else {
                    mma_tf32(acc2[nt], a2h, bh);
                    mma_tf32(acc2[nt], a2h, bl);
                    mma_tf32(acc2[nt], a2l, bh);
                }
            }
        }
    }
}

#define SMEM_SIDE_FLOATS (2 * 32 * SA_STRIDE + 2 * 64 * SW_STRIDE)
#define SMEM_SIDE_BYTES  (SMEM_SIDE_FLOATS * 4)

// ------------------------------ side kernel --------------------------------
template<int SIDE>
__global__ __launch_bounds__(256) void side_kernel(
    const float* __restrict__ ga, const float* __restrict__ gs,
    const float* __restrict__ sscale,
    const float* __restrict__ Wg, const float* __restrict__ bg,
    const float* __restrict__ Wb,
    const float* __restrict__ W1, const float* __restrict__ b1,
    const float* __restrict__ W2,
    float* __restrict__ out1, float* __restrict__ out2) {

    extern __shared__ float smem[];
    float* sA = smem;
    float* sS = smem + 32 * SA_STRIDE;
    float* sW = smem + 2 * 32 * SA_STRIDE;

    const int tid = threadIdx.x;
    const int lane = tid & 31, warp = tid >> 5;
    const int gid = lane >> 2, ctg = lane & 3;
    const int r0 = (warp & 1) * 16;
    const int c0 = (warp >> 1) * 32;
    const int row0 = blockIdx.x * 32;

    {
        float4 sc = ((const float4*)sscale)[lane];
        #pragma unroll
        for (int rr = 0; rr < 4; rr++) {
            int lrow = rr * 8 + warp;
            const float4* ap = (const float4*)(ga + (size_t)(row0 + lrow) * CDIM);
            const float4* sp = (const float4*)(gs + (size_t)(row0 + lrow) * CDIM);
            float4 av = ap[lane];
            float4 sv = sp[lane];
            float s1 = av.x + av.y + av.z + av.w;
            float s2 = av.x*av.x + av.y*av.y + av.z*av.z + av.w*av.w;
            float t1 = sv.x + sv.y + sv.z + sv.w;
            float t2 = sv.x*sv.x + sv.y*sv.y + sv.z*sv.z + sv.w*sv.w;
            #pragma unroll
            for (int o = 16; o > 0; o >>= 1) {
                s1 += __shfl_xor_sync(~0u, s1, o);
                s2 += __shfl_xor_sync(~0u, s2, o);
                t1 += __shfl_xor_sync(~0u, t1, o);
                t2 += __shfl_xor_sync(~0u, t2, o);
            }
            float ma = s1 * (1.f/CDIM);
            float ra = rsqrtf(s2 * (1.f/CDIM) - ma*ma + EPS);
            float ms = t1 * (1.f/CDIM);
            float rs = rsqrtf(t2 * (1.f/CDIM) - ms*ms + EPS);
            float* pa = sA + lrow * SA_STRIDE + lane * 4;
            float* ps = sS + lrow * SA_STRIDE + lane * 4;
            pa[0] = (av.x - ma) * ra; pa[1] = (av.y - ma) * ra;
            pa[2] = (av.z - ma) * ra; pa[3] = (av.w - ma) * ra;
            ps[0] = (sv.x - ms) * rs * sc.x; ps[1] = (sv.y - ms) * rs * sc.y;
            ps[2] = (sv.z - ms) * rs * sc.z; ps[3] = (sv.w - ms) * rs * sc.w;
        }
    }
    __syncthreads();

    float accG[4][4], accB[4][4];
    gemm_dual<true>(sS, sS, Wg, Wb, sW, tid, accG, accB);

    __syncthreads();
    #pragma unroll
    for (int nt = 0; nt < 4; nt++) {
        int col = c0 + nt * 8 + 2 * ctg;
        float bg0 = bg[col], bg1 = bg[col + 1];
        #pragma unroll
        for (int i = 0; i < 2; i++) {
            int lrow = r0 + gid + i * 8;
            float* pr = sS + lrow * SA_STRIDE + col;
            const float* pl = sA + lrow * SA_STRIDE + col;
            pr[0] = sigmoidf_(accG[nt][2*i]   + bg0) * pl[0] + accB[nt][2*i];
            pr[1] = sigmoidf_(accG[nt][2*i+1] + bg1) * pl[1] + accB[nt][2*i+1];
        }
    }

    float acc1[4][4], acc2[4][4];
    gemm_dual<true>(sS, sS, W1, W2, sW, tid, acc1, acc2);

    #pragma unroll
    for (int nt = 0; nt < 4; nt++) {
        int col = c0 + nt * 8 + 2 * ctg;
        float bb0 = 0.f, bb1 = 0.f;
        if (SIDE == 0) { bb0 = b1[col]; bb1 = b1[col + 1]; }
        #pragma unroll
        for (int i = 0; i < 2; i++) {
            int grow = row0 + r0 + gid + i * 8;
            size_t idx = (size_t)grow * CDIM + col;
            if (SIDE == 0) {
                out1[idx]     = (acc1[nt][2*i]   + bb0) * QK_SCALE;
                out1[idx + 1] = (acc1[nt][2*i+1] + bb1) * QK_SCALE;
                out2[idx]     = sigmoidf_(acc2[nt][2*i]);
                out2[idx + 1] = sigmoidf_(acc2[nt][2*i+1]);
            } else {
                out1[idx]     = acc1[nt][2*i];
                out1[idx + 1] = acc1[nt][2*i+1];
                out2[idx]     = acc2[nt][2*i];
                out2[idx + 1] = acc2[nt][2*i+1];
            }
        }
    }
}

// ------------------------------ final kernel -------------------------------
__global__ __launch_bounds__(256) void final_kernel(
    const float* __restrict__ og, const float* __restrict__ sq,
    const float* __restrict__ Wo, const float* __restrict__ Ws,
    const float* __restrict__ bs, float* __restrict__ out) {

    extern __shared__ float smem[];
    float* sA1 = smem;
    float* sA2 = smem + 32 * SA_STRIDE;
    float* sW  = smem + 2 * 32 * SA_STRIDE;

    const int tid = threadIdx.x;
    const int lane = tid & 31, warp = tid >> 5;
    const int gid = lane >> 2, ctg = lane & 3;
    const int r0 = (warp & 1) * 16;
    const int c0 = (warp >> 1) * 32;
    const int row0 = blockIdx.x * 32;

    #pragma unroll
    for (int i = 0; i < 4; i++) {
        int e = tid + i * 256;
        int r = e >> 5, c4 = e & 31;
        cp16(sA1 + r * SA_STRIDE + c4 * 4, og + (size_t)(row0 + r) * CDIM + c4 * 4);
        cp16(sA2 + r * SA_STRIDE + c4 * 4, sq + (size_t)(row0 + r) * CDIM + c4 * 4);
    }
    asm volatile("cp.async.commit_group;\ncp.async.wait_group 0;" ::: "memory");

    float acc1[4][4], acc2[4][4];
    gemm_dual<false>(sA1, sA2, Wo, Ws, sW, tid, acc1, acc2);

    #pragma unroll
    for (int nt = 0; nt < 4; nt++) {
        int col = c0 + nt * 8 + 2 * ctg;
        float b0 = bs[col], b1 = bs[col + 1];
        #pragma unroll
        for (int i = 0; i < 2; i++) {
            int grow = row0 + r0 + gid + i * 8;
            size_t idx = (size_t)grow * CDIM + col;
            out[idx]     = sigmoidf_(acc2[nt][2*i]   + b0) * acc1[nt][2*i];
            out[idx + 1] = sigmoidf_(acc2[nt][2*i+1] + b1) * acc1[nt][2*i+1];
        }
    }
}

// --------------------------- attention kernel ------------------------------
// 384 threads: warps 0-7 consumers (flash attention), warps 8-11 producers
// (z-bias for next tile into double-buffered Psm).
// Named barriers: 1,2 = full[0,1] (count 384); 3,4 = empty[0,1] (count 384);
//                 5 = consumer-only K/V reuse guard (count 256).
#define K_STRIDE 132
#define V_STRIDE 136
#define P_STRIDE 68
#define PBUF (NHEAD * 32 * P_STRIDE)
#define SMEM_FLOATS (64 * K_STRIDE + 64 * V_STRIDE + 2 * PBUF)
#define SMEM_BYTES  (SMEM_FLOATS * 4)
#define NTILES (NSEQ / 64)

__global__ __launch_bounds__(384, 1) void attn_kernel(
    const float* __restrict__ z,
    const float* __restrict__ gq, const float* __restrict__ gk,
    const float* __restrict__ gv, const float* __restrict__ gg,
    float* __restrict__ og) {

    extern __shared__ float smem[];
    float* Ksm = smem;
    float* Vsm = smem + 64 * K_STRIDE;
    float* Psm = Vsm + 64 * V_STRIDE;

    const int tid = threadIdx.x;
    const int qg0 = blockIdx.x * 32;

    if (tid >= 256) {
        // ======================= PRODUCER warps =======================
        const int ptid = tid - 256;
        const int kk0 = ptid & 63;           // key column within tile
        const int qq0 = ptid >> 6;           // 0 or 1; q = qq0 + 2*qi
        const float csum0 = c_bias[64], csum1 = c_bias[65];
        const float csum2 = c_bias[66], csum3 = c_bias[67];

        // 2-deep rolling z prefetch across the whole tile sequence
        float4 zb[2][4];
        #pragma unroll
        for (int u = 0; u < 2; u++) {
            const float4* zp = (const float4*)(z + ((size_t)(qg0 + qq0 + u * 2) * NSEQ + kk0) * CZ);
            zb[u][0] = zp[0]; zb[u][1] = zp[1]; zb[u][2] = zp[2]; zb[u][3] = zp[3];
        }

        for (int t = 0; t < NTILES; t++) {
            float* Pbuf = Psm + (t & 1) * PBUF;
            if (t >= 2)
                asm volatile("bar.sync %0, 384;" :: "r"(3 + (t & 1)) : "memory");
            const int kb = t * 64;
            #pragma unroll 4
            for (int qi = 0; qi < 16; qi++) {
                const int pb2 = qi & 1;      // t*16 even -> (u&1) == (qi&1)
                float4 zc[4] = { zb[pb2][0], zb[pb2][1], zb[pb2][2], zb[pb2][3] };
                // prefetch u+2
                {
                    int qin = (qi + 2) & 15;
                    int kbn = kb + (((qi + 2) >> 4) << 6);
                    if (kbn >= NSEQ) kbn = 0;   // tail: harmless valid reload
                    const float4* zn = (const float4*)(z + ((size_t)(qg0 + qq0 + qin * 2) * NSEQ + kbn + kk0) * CZ);
                    zb[pb2][0] = zn[0]; zb[pb2][1] = zn[1];
                    zb[pb2][2] = zn[2]; zb[pb2][3] = zn[3];
                }
                float s1 = 0.f, s2 = 0.f, d0 = 0.f, d1 = 0.f, d2 = 0.f, d3 = 0.f;
                #pragma unroll
                for (int j = 0; j < 4; j++) {
                    float4 v = zc[j];
                    int cb = j * 4;
                    s1 += v.x + v.y + v.z + v.w;
                    s2 += v.x*v.x + v.y*v.y + v.z*v.z + v.w*v.w;
                    d0 += v.x*c_bias[(cb+0)*4+0]; d1 += v.x*c_bias[(cb+0)*4+1];
                    d2 += v.x*c_bias[(cb+0)*4+2]; d3 += v.x*c_bias[(cb+0)*4+3];
                    d0 += v.y*c_bias[(cb+1)*4+0]; d1 += v.y*c_bias[(cb+1)*4+1];
                    d2 += v.y*c_bias[(cb+1)*4+2]; d3 += v.y*c_bias[(cb+1)*4+3];
                    d0 += v.z*c_bias[(cb+2)*4+0]; d1 += v.z*c_bias[(cb+2)*4+1];
                    d2 += v.z*c_bias[(cb+2)*4+2]; d3 += v.z*c_bias[(cb+2)*4+3];
                    d0 += v.w*c_bias[(cb+3)*4+0]; d1 += v.w*c_bias[(cb+3)*4+1];
                    d2 += v.w*c_bias[(cb+3)*4+2]; d3 += v.w*c_bias[(cb+3)*4+3];
                }
                float mm = s1 * (1.f/CZ);
                float rstd = rsqrtf(s2 * (1.f/CZ) - mm * mm + EPS);
                int q = qq0 + qi * 2;
                float* pb = Pbuf + q * P_STRIDE + kk0;
                pb[0 * 32 * P_STRIDE] = (d0 - mm * csum0) * rstd;
                pb[1 * 32 * P_STRIDE] = (d1 - mm * csum1) * rstd;
                pb[2 * 32 * P_STRIDE] = (d2 - mm * csum2) * rstd;
                pb[3 * 32 * P_STRIDE] = (d3 - mm * csum3) * rstd;
            }
            asm volatile("bar.arrive %0, 384;" :: "r"(1 + (t & 1)) : "memory");
        }
        return;
    }

    // ======================= CONSUMER warps =======================
    const int lane = tid & 31, warp = tid >> 5;
    const int h = warp >> 1, qh = warp & 1;
    const int gid = lane >> 2, ctg = lane & 3;

    // Q fragments (A of m16n8k8 tf32), q pre-scaled by 1/sqrt(c)
    uint32_t qa[4][4];
    {
        int r0 = qg0 + qh * 16 + gid;
        const float* qp = gq + (size_t)r0 * CDIM + h * HDIM + ctg;
        #pragma unroll
        for (int ks = 0; ks < 4; ks++) {
            qa[ks][0] = f2tf32(qp[ks*8]);
            qa[ks][1] = f2tf32(qp[8*CDIM + ks*8]);
            qa[ks][2] = f2tf32(qp[ks*8 + 4]);
            qa[ks][3] = f2tf32(qp[8*CDIM + ks*8 + 4]);
        }
    }

    float O[4][4];
    #pragma unroll
    for (int i = 0; i < 4; i++) { O[i][0]=O[i][1]=O[i][2]=O[i][3]=0.f; }
    float m1 = -1e30f, m2 = -1e30f, l1 = 0.f, l2 = 0.f;

    for (int t = 0; t < NTILES; t++) {
        const int kb = t * 64;
        // all consumers done reading previous K/V tile
        asm volatile("bar.sync 5, 256;" ::: "memory");

        // prefetch K/V tile (256 consumer threads)
        #pragma unroll
        for (int i = 0; i < 8; i++) {
            int e = tid + i * 256;
            int r = e >> 5, c4 = e & 31;
            cp16(Ksm + r * K_STRIDE + c4 * 4, gk + (size_t)(kb + r) * CDIM + c4 * 4);
        }
        #pragma unroll
        for (int i = 0; i < 8; i++) {
            int e = tid + i * 256;
            int r = e >> 5, c4 = e & 31;
            cp16(Vsm + r * V_STRIDE + c4 * 4, gv + (size_t)(kb + r) * CDIM + c4 * 4);
        }
        asm volatile("cp.async.commit_group;\ncp.async.wait_group 0;" ::: "memory");

        // wait for producers' bias tile (also rendezvous: everyone's cp.async done)
        asm volatile("bar.sync %0, 384;" :: "r"(1 + (t & 1)) : "memory");
        float* Pbuf = Psm + (t & 1) * PBUF;

        // ---- QK^T (tf32 mma): S[16q x 64k] per warp
        float S[8][4];
        #pragma unroll
        for (int nt = 0; nt < 8; nt++) {
            S[nt][0] = S[nt][1] = S[nt][2] = S[nt][3] = 0.f;
            const float* kp = Ksm + (nt * 8 + gid) * K_STRIDE + h * HDIM + ctg;
            #pragma unroll
            for (int ks = 0; ks < 4; ks++) {
                uint32_t b[2];
                b[0] = __float_as_uint(kp[ks * 8]);
                b[1] = __float_as_uint(kp[ks * 8 + 4]);
                mma_tf32(S[nt], qa[ks], b);
            }
        }

        // ---- bias add + online softmax
        float* pwarp = Pbuf + h * 32 * P_STRIDE + (qh * 16) * P_STRIDE;
        float mx1 = -1e30f, mx2 = -1e30f;
        #pragma unroll
        for (int nt = 0; nt < 8; nt++) {
            int col = nt * 8 + 2 * ctg;
            S[nt][0] += pwarp[gid * P_STRIDE + col];
            S[nt][1] += pwarp[gid * P_STRIDE + col + 1];
            S[nt][2] += pwarp[(gid + 8) * P_STRIDE + col];
            S[nt][3] += pwarp[(gid + 8) * P_STRIDE + col + 1];
            mx1 = fmaxf(mx1, fmaxf(S[nt][0], S[nt][1]));
            mx2 = fmaxf(mx2, fmaxf(S[nt][2], S[nt][3]));
        }
        mx1 = fmaxf(mx1, __shfl_xor_sync(~0u, mx1, 1));
        mx1 = fmaxf(mx1, __shfl_xor_sync(~0u, mx1, 2));
        mx2 = fmaxf(mx2, __shfl_xor_sync(~0u, mx2, 1));
        mx2 = fmaxf(mx2, __shfl_xor_sync(~0u, mx2, 2));
        float mn1 = fmaxf(m1, mx1), mn2 = fmaxf(m2, mx2);
        float al1 = __expf(m1 - mn1), al2 = __expf(m2 - mn2);
        float rs1 = 0.f, rs2 = 0.f;
        #pragma unroll
        for (int nt = 0; nt < 8; nt++) {
            float p0 = __expf(S[nt][0] - mn1);
            float p1 = __expf(S[nt][1] - mn1);
            float p2 = __expf(S[nt][2] - mn2);
            float p3 = __expf(S[nt][3] - mn2);
            rs1 += p0 + p1; rs2 += p2 + p3;
            int col = nt * 8 + 2 * ctg;
            pwarp[gid * P_STRIDE + col]           = __uint_as_float(f2tf32(p0));
            pwarp[gid * P_STRIDE + col + 1]       = __uint_as_float(f2tf32(p1));
            pwarp[(gid + 8) * P_STRIDE + col]     = __uint_as_float(f2tf32(p2));
            pwarp[(gid + 8) * P_STRIDE + col + 1] = __uint_as_float(f2tf32(p3));
        }
        rs1 += __shfl_xor_sync(~0u, rs1, 1); rs1 += __shfl_xor_sync(~0u, rs1, 2);
        rs2 += __shfl_xor_sync(~0u, rs2, 1); rs2 += __shfl_xor_sync(~0u, rs2, 2);
        l1 = l1 * al1 + rs1; l2 = l2 * al2 + rs2;
        m1 = mn1; m2 = mn2;
        #pragma unroll
        for (int on = 0; on < 4; on++) {
            O[on][0] *= al1; O[on][1] *= al1; O[on][2] *= al2; O[on][3] *= al2;
        }
        __syncwarp();

        // ---- PV (tf32 mma): O[16q x 32c] += P[16q x 64k] @ V[64k x 32c]
        #pragma unroll
        for (int on = 0; on < 4; on++) {
            #pragma unroll
            for (int ks = 0; ks < 8; ks++) {
                uint32_t a[4], b[2];
                const float* pp = pwarp + gid * P_STRIDE + ks * 8 + ctg;
                a[0] = __float_as_uint(pp[0]);
                a[1] = __float_as_uint(pp[8 * P_STRIDE]);
                a[2] = __float_as_uint(pp[4]);
                a[3] = __float_as_uint(pp[8 * P_STRIDE + 4]);
                const float* vp = Vsm + (ks * 8 + ctg) * V_STRIDE + h * HDIM + on * 8 + gid;
                b[0] = __float_as_uint(vp[0]);
                b[1] = __float_as_uint(vp[4 * V_STRIDE]);
                mma_tf32(O[on], a, b);
            }
        }
        // release Psm buffer to producers
        asm volatile("bar.arrive %0, 384;" :: "r"(3 + (t & 1)) : "memory");
    }

    // ---- epilogue: normalize, gate, store
    float r1 = 1.f / l1, r2 = 1.f / l2;
    int row1 = qg0 + qh * 16 + gid, row2 = row1 + 8;
    #pragma unroll
    for (int on = 0; on < 4; on++) {
        int col = h * HDIM + on * 8 + 2 * ctg;
        size_t i1 = (size_t)row1 * CDIM + col;
        size_t i2 = (size_t)row2 * CDIM + col;
        og[i1]     = O[on][0] * r1 * gg[i1];
        og[i1 + 1] = O[on][1] * r1 * gg[i1 + 1];
        og[i2]     = O[on][2] * r2 * gg[i2];
        og[i2 + 1] = O[on][3] * r2 * gg[i2 + 1];
    }
}

// ------------------------------ launch -------------------------------------
extern "C" void kernel_launch(void* const* d_in, const int* in_sizes, int n_in,
                              void* d_out, int out_size) {
    const float* a_q      = (const float*)d_in[0];
    const float* a_k      = (const float*)d_in[1];
    const float* z        = (const float*)d_in[2];
    const float* s_q      = (const float*)d_in[3];
    const float* s_k      = (const float*)d_in[4];
    const float* Wg_q     = (const float*)d_in[5];
    const float* bg_q     = (const float*)d_in[6];
    const float* Wb_q     = (const float*)d_in[7];
    const float* sscale_q = (const float*)d_in[8];
    const float* Wg_k     = (const float*)d_in[9];
    const float* bg_k     = (const float*)d_in[10];
    const float* Wb_k     = (const float*)d_in[11];
    const float* sscale_k = (const float*)d_in[12];
    const float* lnz      = (const float*)d_in[13];
    const float* Wq       = (const float*)d_in[14];
    const float* bq       = (const float*)d_in[15];
    const float* Wk       = (const float*)d_in[16];
    const float* Wv       = (const float*)d_in[17];
    const float* Wbias    = (const float*)d_in[18];
    const float* Wgate    = (const float*)d_in[19];
    const float* Wo       = (const float*)d_in[20];
    const float* Ws       = (const float*)d_in[21];
    const float* bs       = (const float*)d_in[22];

    float* scratch = nullptr;
    cudaGetSymbolAddress((void**)&scratch, g_scratch);
    const size_t SL = (size_t)NSEQ * CDIM;
    float* qbuf  = scratch + 0 * SL;
    float* gbuf  = scratch + 1 * SL;
    float* kbuf  = scratch + 2 * SL;
    float* vbuf  = scratch + 3 * SL;
    float* ogbuf = scratch + 4 * SL;
    float* biasw = scratch + 5 * SL;

    init_bias<<<1, 96>>>(lnz, Wbias, biasw);
    cudaMemcpyToSymbolAsync(c_bias, biasw, (CZ * NHEAD + NHEAD) * sizeof(float), 0,
                            cudaMemcpyDeviceToDevice, 0);

    cudaFuncSetAttribute(side_kernel<0>, cudaFuncAttributeMaxDynamicSharedMemorySize,
                         SMEM_SIDE_BYTES);
    cudaFuncSetAttribute(side_kernel<1>, cudaFuncAttributeMaxDynamicSharedMemorySize,
                         SMEM_SIDE_BYTES);
    cudaFuncSetAttribute(final_kernel, cudaFuncAttributeMaxDynamicSharedMemorySize,
                         SMEM_SIDE_BYTES);
    cudaFuncSetAttribute(attn_kernel, cudaFuncAttributeMaxDynamicSharedMemorySize,
                         SMEM_BYTES);

    side_kernel<0><<<NSEQ / 32, 256, SMEM_SIDE_BYTES>>>(
        a_q, s_q, sscale_q, Wg_q, bg_q, Wb_q, Wq, bq, Wgate, qbuf, gbuf);
    side_kernel<1><<<NSEQ / 32, 256, SMEM_SIDE_BYTES>>>(
        a_k, s_k, sscale_k, Wg_k, bg_k, Wb_k, Wk, nullptr, Wv, kbuf, vbuf);

    attn_kernel<<<NSEQ / 32, 384, SMEM_BYTES>>>(z, qbuf, kbuf, vbuf, gbuf, ogbuf);

    final_kernel<<<NSEQ / 32, 256, SMEM_SIDE_BYTES>>>(
        ogbuf, s_q, Wo, Ws, bs, (float*)d_out);
}

// round 7
// speedup vs baseline: 1.1818x; 1.0046x over previous
#include <cuda_runtime.h>
#include <cuda_bf16.h>
#include <cstdint>
#include <cstdio>

// ---------------------------------------------------------------------------
// AtomAttentionPairBias: B=1, Nq=Nk=4096, C=128, H=4, c=32, CZ=16  (all fp32)
//
//   1. init_bias: premultiply lnz*Wbias -> constant bank
//   2. side_kernel<Q/K>: LN -> AdaLN -> {q,gate} / {k,v}; split-tf32 mma
//   3. attn_kernel (WARP-SPECIALIZED): 8 consumer warps do flash attention
//      (tf32 mma QK^T / PV, online softmax); 4 producer warps stream z ONCE
//      and compute the fused LN(z)@Wbias bias for the NEXT tile into a
//      double-buffered Psm. Named-barrier full/empty handshake.
//   4. final_kernel: out = sigmoid(s_q@Ws+bs) * (og@Wo), split-tf32
// ---------------------------------------------------------------------------

#define NSEQ 4096
#define CDIM 128
#define NHEAD 4
#define HDIM 32
#define CZ 16
#define EPS 1e-5f
#define QK_SCALE 0.17677669529663687f   // 1/sqrt(32)

__device__ float g_scratch[6u * NSEQ * CDIM];

// c_bias[0..63]  = lnz[c] * Wbias[c][h]  (row-major [cz][h])
// c_bias[64..67] = per-head column sums of the above
__constant__ float c_bias[CZ * NHEAD + NHEAD];

__device__ __forceinline__ float sigmoidf_(float x) { return 1.f / (1.f + __expf(-x)); }

__device__ __forceinline__ uint32_t f2tf32(float x) {
    uint32_t y; asm("cvt.rna.tf32.f32 %0, %1;" : "=r"(y) : "f"(x)); return y;
}
__device__ __forceinline__ void mma_tf32(float* d, const uint32_t* a, const uint32_t* b) {
    asm volatile("mma.sync.aligned.m16n8k8.row.col.f32.tf32.tf32.f32 "
                 "{%0,%1,%2,%3}, {%4,%5,%6,%7}, {%8,%9}, {%0,%1,%2,%3};"
                 : "+f"(d[0]), "+f"(d[1]), "+f"(d[2]), "+f"(d[3])
                 : "r"(a[0]), "r"(a[1]), "r"(a[2]), "r"(a[3]), "r"(b[0]), "r"(b[1]));
}
__device__ __forceinline__ void cp16(float* dst, const float* src) {
    uint32_t d = (uint32_t)__cvta_generic_to_shared(dst);
    asm volatile("cp.async.cg.shared.global [%0], [%1], 16;" :: "r"(d), "l"(src));
}

// ------------------------------ init_bias ----------------------------------
__global__ void init_bias(const float* __restrict__ lnz, const float* __restrict__ wb,
                          float* __restrict__ out) {
    int t = threadIdx.x;
    if (t < 64) out[t] = lnz[t >> 2] * wb[t];
    if (t >= 64 && t < 68) {
        int h = t - 64;
        float s = 0.f;
        for (int c = 0; c < CZ; c++) s += lnz[c] * wb[c * 4 + h];
        out[t] = s;
    }
}

// ------------------- split-tf32 dual GEMM tile helper -----------------------
#define SA_STRIDE 132
#define SW_STRIDE 136

template<bool SAME_A>
__device__ __forceinline__ void gemm_dual(
    const float* __restrict__ sA1, const float* __restrict__ sA2,
    const float* __restrict__ gW1, const float* __restrict__ gW2,
    float* sW, int tid, float acc1[4][4], float acc2[4][4]) {

    const int lane = tid & 31, warp = tid >> 5;
    const int gid = lane >> 2, ctg = lane & 3;
    const int r0 = (warp & 1) * 16;
    const int c0 = (warp >> 1) * 32;

    #pragma unroll
    for (int nt = 0; nt < 4; nt++)
        #pragma unroll
        for (int j = 0; j < 4; j++) { acc1[nt][j] = 0.f; acc2[nt][j] = 0.f; }

    for (int kc = 0; kc < CDIM; kc += 64) {
        __syncthreads();   // protect sW from previous chunk's readers
        #pragma unroll
        for (int i = 0; i < 8; i++) {
            int e = tid + i * 256;
            int r = e >> 5, c4 = e & 31;
            cp16(sW + r * SW_STRIDE + c4 * 4, gW1 + (size_t)(kc + r) * CDIM + c4 * 4);
            cp16(sW + 64 * SW_STRIDE + r * SW_STRIDE + c4 * 4,
                 gW2 + (size_t)(kc + r) * CDIM + c4 * 4);
        }
        asm volatile("cp.async.commit_group;\ncp.async.wait_group 0;" ::: "memory");
        __syncthreads();

        #pragma unroll
        for (int ks = 0; ks < 8; ks++) {
            int kg = kc + ks * 8;
            uint32_t a1h[4], a1l[4], a2h[4], a2l[4];
            {
                const float* ap = sA1 + (r0 + gid) * SA_STRIDE + kg + ctg;
                float x;
                x = ap[0];               a1h[0] = f2tf32(x); a1l[0] = f2tf32(x - __uint_as_float(a1h[0]));
                x = ap[8 * SA_STRIDE];   a1h[1] = f2tf32(x); a1l[1] = f2tf32(x - __uint_as_float(a1h[1]));
                x = ap[4];               a1h[2] = f2tf32(x); a1l[2] = f2tf32(x - __uint_as_float(a1h[2]));
                x = ap[8 * SA_STRIDE+4]; a1h[3] = f2tf32(x); a1l[3] = f2tf32(x - __uint_as_float(a1h[3]));
            }
            if (!SAME_A) {
                const float* ap = sA2 + (r0 + gid) * SA_STRIDE + kg + ctg;
                float x;
                x = ap[0];               a2h[0] = f2tf32(x); a2l[0] = f2tf32(x - __uint_as_float(a2h[0]));
                x = ap[8 * SA_STRIDE];   a2h[1] = f2tf32(x); a2l[1] = f2tf32(x - __uint_as_float(a2h[1]));
                x = ap[4];               a2h[2] = f2tf32(x); a2l[2] = f2tf32(x - __uint_as_float(a2h[2]));
                x = ap[8 * SA_STRIDE+4]; a2h[3] = f2tf32(x); a2l[3] = f2tf32(x - __uint_as_float(a2h[3]));
            }
            #pragma unroll
            for (int nt = 0; nt < 4; nt++) {
                const float* bp = sW + (ks * 8 + ctg) * SW_STRIDE + c0 + nt * 8 + gid;
                uint32_t bh[2], bl[2];
                float b0 = bp[0], b1 = bp[4 * SW_STRIDE];
                bh[0] = f2tf32(b0); bl[0] = f2tf32(b0 - __uint_as_float(bh[0]));
                bh[1] = f2tf32(b1); bl[1] = f2tf32(b1 - __uint_as_float(bh[1]));
                mma_tf32(acc1[nt], a1h, bh);
                mma_tf32(acc1[nt], a1h, bl);
                mma_tf32(acc1[nt], a1l, bh);
                const float* bp2 = bp + 64 * SW_STRIDE;
                b0 = bp2[0]; b1 = bp2[4 * SW_STRIDE];
                bh[0] = f2tf32(b0); bl[0] = f2tf32(b0 - __uint_as_float(bh[0]));
                bh[1] = f2tf32(b1); bl[1] = f2tf32(b1 - __uint_as_float(bh[1]));
                if (SAME_A) {
                    mma_tf32(acc2[nt], a1h, bh);
                    mma_tf32(acc2[nt], a1h, bl);
                    mma_tf32(acc2[nt], a1l, bh);
                } else {
                    mma_tf32(acc2[nt], a2h, bh);
                    mma_tf32(acc2[nt], a2h, bl);
                    mma_tf32(acc2[nt], a2l, bh);
                }
            }
        }
    }
}

#define SMEM_SIDE_FLOATS (2 * 32 * SA_STRIDE + 2 * 64 * SW_STRIDE)
#define SMEM_SIDE_BYTES  (SMEM_SIDE_FLOATS * 4)

// ------------------------------ side kernel --------------------------------
template<int SIDE>
__global__ __launch_bounds__(256) void side_kernel(
    const float* __restrict__ ga, const float* __restrict__ gs,
    const float* __restrict__ sscale,
    const float* __restrict__ Wg, const float* __restrict__ bg,
    const float* __restrict__ Wb,
    const float* __restrict__ W1, const float* __restrict__ b1,
    const float* __restrict__ W2,
    float* __restrict__ out1, float* __restrict__ out2) {

    extern __shared__ float smem[];
    float* sA = smem;
    float* sS = smem + 32 * SA_STRIDE;
    float* sW = smem + 2 * 32 * SA_STRIDE;

    const int tid = threadIdx.x;
    const int lane = tid & 31, warp = tid >> 5;
    const int gid = lane >> 2, ctg = lane & 3;
    const int r0 = (warp & 1) * 16;
    const int c0 = (warp >> 1) * 32;
    const int row0 = blockIdx.x * 32;

    {
        float4 sc = ((const float4*)sscale)[lane];
        #pragma unroll
        for (int rr = 0; rr < 4; rr++) {
            int lrow = rr * 8 + warp;
            const float4* ap = (const float4*)(ga + (size_t)(row0 + lrow) * CDIM);
            const float4* sp = (const float4*)(gs + (size_t)(row0 + lrow) * CDIM);
            float4 av = ap[lane];
            float4 sv = sp[lane];
            float s1 = av.x + av.y + av.z + av.w;
            float s2 = av.x*av.x + av.y*av.y + av.z*av.z + av.w*av.w;
            float t1 = sv.x + sv.y + sv.z + sv.w;
            float t2 = sv.x*sv.x + sv.y*sv.y + sv.z*sv.z + sv.w*sv.w;
            #pragma unroll
            for (int o = 16; o > 0; o >>= 1) {
                s1 += __shfl_xor_sync(~0u, s1, o);
                s2 += __shfl_xor_sync(~0u, s2, o);
                t1 += __shfl_xor_sync(~0u, t1, o);
                t2 += __shfl_xor_sync(~0u, t2, o);
            }
            float ma = s1 * (1.f/CDIM);
            float ra = rsqrtf(s2 * (1.f/CDIM) - ma*ma + EPS);
            float ms = t1 * (1.f/CDIM);
            float rs = rsqrtf(t2 * (1.f/CDIM) - ms*ms + EPS);
            float* pa = sA + lrow * SA_STRIDE + lane * 4;
            float* ps = sS + lrow * SA_STRIDE + lane * 4;
            pa[0] = (av.x - ma) * ra; pa[1] = (av.y - ma) * ra;
            pa[2] = (av.z - ma) * ra; pa[3] = (av.w - ma) * ra;
            ps[0] = (sv.x - ms) * rs * sc.x; ps[1] = (sv.y - ms) * rs * sc.y;
            ps[2] = (sv.z - ms) * rs * sc.z; ps[3] = (sv.w - ms) * rs * sc.w;
        }
    }
    __syncthreads();

    float accG[4][4], accB[4][4];
    gemm_dual<true>(sS, sS, Wg, Wb, sW, tid, accG, accB);

    __syncthreads();
    #pragma unroll
    for (int nt = 0; nt < 4; nt++) {
        int col = c0 + nt * 8 + 2 * ctg;
        float bg0 = bg[col], bg1 = bg[col + 1];
        #pragma unroll
        for (int i = 0; i < 2; i++) {
            int lrow = r0 + gid + i * 8;
            float* pr = sS + lrow * SA_STRIDE + col;
            const float* pl = sA + lrow * SA_STRIDE + col;
            pr[0] = sigmoidf_(accG[nt][2*i]   + bg0) * pl[0] + accB[nt][2*i];
            pr[1] = sigmoidf_(accG[nt][2*i+1] + bg1) * pl[1] + accB[nt][2*i+1];
        }
    }

    float acc1[4][4], acc2[4][4];
    gemm_dual<true>(sS, sS, W1, W2, sW, tid, acc1, acc2);

    #pragma unroll
    for (int nt = 0; nt < 4; nt++) {
        int col = c0 + nt * 8 + 2 * ctg;
        float bb0 = 0.f, bb1 = 0.f;
        if (SIDE == 0) { bb0 = b1[col]; bb1 = b1[col + 1]; }
        #pragma unroll
        for (int i = 0; i < 2; i++) {
            int grow = row0 + r0 + gid + i * 8;
            size_t idx = (size_t)grow * CDIM + col;
            if (SIDE == 0) {
                out1[idx]     = (acc1[nt][2*i]   + bb0) * QK_SCALE;
                out1[idx + 1] = (acc1[nt][2*i+1] + bb1) * QK_SCALE;
                out2[idx]     = sigmoidf_(acc2[nt][2*i]);
                out2[idx + 1] = sigmoidf_(acc2[nt][2*i+1]);
            } else {
                out1[idx]     = acc1[nt][2*i];
                out1[idx + 1] = acc1[nt][2*i+1];
                out2[idx]     = acc2[nt][2*i];
                out2[idx + 1] = acc2[nt][2*i+1];
            }
        }
    }
}

// ------------------------------ final kernel -------------------------------
__global__ __launch_bounds__(256) void final_kernel(
    const float* __restrict__ og, const float* __restrict__ sq,
    const float* __restrict__ Wo, const float* __restrict__ Ws,
    const float* __restrict__ bs, float* __restrict__ out) {

    extern __shared__ float smem[];
    float* sA1 = smem;
    float* sA2 = smem + 32 * SA_STRIDE;
    float* sW  = smem + 2 * 32 * SA_STRIDE;

    const int tid = threadIdx.x;
    const int lane = tid & 31, warp = tid >> 5;
    const int gid = lane >> 2, ctg = lane & 3;
    const int r0 = (warp & 1) * 16;
    const int c0 = (warp >> 1) * 32;
    const int row0 = blockIdx.x * 32;

    #pragma unroll
    for (int i = 0; i < 4; i++) {
        int e = tid + i * 256;
        int r = e >> 5, c4 = e & 31;
        cp16(sA1 + r * SA_STRIDE + c4 * 4, og + (size_t)(row0 + r) * CDIM + c4 * 4);
        cp16(sA2 + r * SA_STRIDE + c4 * 4, sq + (size_t)(row0 + r) * CDIM + c4 * 4);
    }
    asm volatile("cp.async.commit_group;\ncp.async.wait_group 0;" ::: "memory");

    float acc1[4][4], acc2[4][4];
    gemm_dual<false>(sA1, sA2, Wo, Ws, sW, tid, acc1, acc2);

    #pragma unroll
    for (int nt = 0; nt < 4; nt++) {
        int col = c0 + nt * 8 + 2 * ctg;
        float b0 = bs[col], b1 = bs[col + 1];
        #pragma unroll
        for (int i = 0; i < 2; i++) {
            int grow = row0 + r0 + gid + i * 8;
            size_t idx = (size_t)grow * CDIM + col;
            out[idx]     = sigmoidf_(acc2[nt][2*i]   + b0) * acc1[nt][2*i];
            out[idx + 1] = sigmoidf_(acc2[nt][2*i+1] + b1) * acc1[nt][2*i+1];
        }
    }
}

// --------------------------- attention kernel ------------------------------
// 384 threads: warps 0-7 consumers (flash attention), warps 8-11 producers
// (z-bias for next tile into double-buffered Psm).
// Named barriers: 1,2 = full[0,1] (count 384); 3,4 = empty[0,1] (count 384);
//                 5 = consumer-only K/V reuse guard (count 256).
#define K_STRIDE 132
#define V_STRIDE 136
#define P_STRIDE 68
#define PBUF (NHEAD * 32 * P_STRIDE)
#define SMEM_FLOATS (64 * K_STRIDE + 64 * V_STRIDE + 2 * PBUF)
#define SMEM_BYTES  (SMEM_FLOATS * 4)
#define NTILES (NSEQ / 64)

__global__ __launch_bounds__(384, 1) void attn_kernel(
    const float* __restrict__ z,
    const float* __restrict__ gq, const float* __restrict__ gk,
    const float* __restrict__ gv, const float* __restrict__ gg,
    float* __restrict__ og) {

    extern __shared__ float smem[];
    float* Ksm = smem;
    float* Vsm = smem + 64 * K_STRIDE;
    float* Psm = Vsm + 64 * V_STRIDE;

    const int tid = threadIdx.x;
    const int qg0 = blockIdx.x * 32;

    if (tid >= 256) {
        // ======================= PRODUCER warps =======================
        const int ptid = tid - 256;
        const int kk0 = ptid & 63;           // key column within tile
        const int qq0 = ptid >> 6;           // 0 or 1; q = qq0 + 2*qi
        const float csum0 = c_bias[64], csum1 = c_bias[65];
        const float csum2 = c_bias[66], csum3 = c_bias[67];

        // 2-deep rolling z prefetch across the whole tile sequence
        float4 zb[2][4];
        #pragma unroll
        for (int u = 0; u < 2; u++) {
            const float4* zp = (const float4*)(z + ((size_t)(qg0 + qq0 + u * 2) * NSEQ + kk0) * CZ);
            zb[u][0] = zp[0]; zb[u][1] = zp[1]; zb[u][2] = zp[2]; zb[u][3] = zp[3];
        }

        for (int t = 0; t < NTILES; t++) {
            float* Pbuf = Psm + (t & 1) * PBUF;
            if (t >= 2)
                asm volatile("bar.sync %0, 384;" :: "r"(3 + (t & 1)) : "memory");
            const int kb = t * 64;
            #pragma unroll 4
            for (int qi = 0; qi < 16; qi++) {
                const int pb2 = qi & 1;      // t*16 even -> (u&1) == (qi&1)
                float4 zc[4] = { zb[pb2][0], zb[pb2][1], zb[pb2][2], zb[pb2][3] };
                // prefetch u+2
                {
                    int qin = (qi + 2) & 15;
                    int kbn = kb + (((qi + 2) >> 4) << 6);
                    if (kbn >= NSEQ) kbn = 0;   // tail: harmless valid reload
                    const float4* zn = (const float4*)(z + ((size_t)(qg0 + qq0 + qin * 2) * NSEQ + kbn + kk0) * CZ);
                    zb[pb2][0] = zn[0]; zb[pb2][1] = zn[1];
                    zb[pb2][2] = zn[2]; zb[pb2][3] = zn[3];
                }
                float s1 = 0.f, s2 = 0.f, d0 = 0.f, d1 = 0.f, d2 = 0.f, d3 = 0.f;
                #pragma unroll
                for (int j = 0; j < 4; j++) {
                    float4 v = zc[j];
                    int cb = j * 4;
                    s1 += v.x + v.y + v.z + v.w;
                    s2 += v.x*v.x + v.y*v.y + v.z*v.z + v.w*v.w;
                    d0 += v.x*c_bias[(cb+0)*4+0]; d1 += v.x*c_bias[(cb+0)*4+1];
                    d2 += v.x*c_bias[(cb+0)*4+2]; d3 += v.x*c_bias[(cb+0)*4+3];
                    d0 += v.y*c_bias[(cb+1)*4+0]; d1 += v.y*c_bias[(cb+1)*4+1];
                    d2 += v.y*c_bias[(cb+1)*4+2]; d3 += v.y*c_bias[(cb+1)*4+3];
                    d0 += v.z*c_bias[(cb+2)*4+0]; d1 += v.z*c_bias[(cb+2)*4+1];
                    d2 += v.z*c_bias[(cb+2)*4+2]; d3 += v.z*c_bias[(cb+2)*4+3];
                    d0 += v.w*c_bias[(cb+3)*4+0]; d1 += v.w*c_bias[(cb+3)*4+1];
                    d2 += v.w*c_bias[(cb+3)*4+2]; d3 += v.w*c_bias[(cb+3)*4+3];
                }
                float mm = s1 * (1.f/CZ);
                float rstd = rsqrtf(s2 * (1.f/CZ) - mm * mm + EPS);
                int q = qq0 + qi * 2;
                float* pb = Pbuf + q * P_STRIDE + kk0;
                pb[0 * 32 * P_STRIDE] = (d0 - mm * csum0) * rstd;
                pb[1 * 32 * P_STRIDE] = (d1 - mm * csum1) * rstd;
                pb[2 * 32 * P_STRIDE] = (d2 - mm * csum2) * rstd;
                pb[3 * 32 * P_STRIDE] = (d3 - mm * csum3) * rstd;
            }
            asm volatile("bar.arrive %0, 384;" :: "r"(1 + (t & 1)) : "memory");
        }
        return;
    }

    // ======================= CONSUMER warps =======================
    const int lane = tid & 31, warp = tid >> 5;
    const int h = warp >> 1, qh = warp & 1;
    const int gid = lane >> 2, ctg = lane & 3;

    // Q fragments (A of m16n8k8 tf32), q pre-scaled by 1/sqrt(c)
    uint32_t qa[4][4];
    {
        int r0 = qg0 + qh * 16 + gid;
        const float* qp = gq + (size_t)r0 * CDIM + h * HDIM + ctg;
        #pragma unroll
        for (int ks = 0; ks < 4; ks++) {
            qa[ks][0] = f2tf32(qp[ks*8]);
            qa[ks][1] = f2tf32(qp[8*CDIM + ks*8]);
            qa[ks][2] = f2tf32(qp[ks*8 + 4]);
            qa[ks][3] = f2tf32(qp[8*CDIM + ks*8 + 4]);
        }
    }

    float O[4][4];
    #pragma unroll
    for (int i = 0; i < 4; i++) { O[i][0]=O[i][1]=O[i][2]=O[i][3]=0.f; }
    float m1 = -1e30f, m2 = -1e30f, l1 = 0.f, l2 = 0.f;

    for (int t = 0; t < NTILES; t++) {
        const int kb = t * 64;
        // all consumers done reading previous K/V tile
        asm volatile("bar.sync 5, 256;" ::: "memory");

        // prefetch K/V tile (256 consumer threads)
        #pragma unroll
        for (int i = 0; i < 8; i++) {
            int e = tid + i * 256;
            int r = e >> 5, c4 = e & 31;
            cp16(Ksm + r * K_STRIDE + c4 * 4, gk + (size_t)(kb + r) * CDIM + c4 * 4);
        }
        #pragma unroll
        for (int i = 0; i < 8; i++) {
            int e = tid + i * 256;
            int r = e >> 5, c4 = e & 31;
            cp16(Vsm + r * V_STRIDE + c4 * 4, gv + (size_t)(kb + r) * CDIM + c4 * 4);
        }
        asm volatile("cp.async.commit_group;\ncp.async.wait_group 0;" ::: "memory");

        // wait for producers' bias tile (also rendezvous: everyone's cp.async done)
        asm volatile("bar.sync %0, 384;" :: "r"(1 + (t & 1)) : "memory");
        float* Pbuf = Psm + (t & 1) * PBUF;

        // ---- QK^T (tf32 mma): S[16q x 64k] per warp
        float S[8][4];
        #pragma unroll
        for (int nt = 0; nt < 8; nt++) {
            S[nt][0] = S[nt][1] = S[nt][2] = S[nt][3] = 0.f;
            const float* kp = Ksm + (nt * 8 + gid) * K_STRIDE + h * HDIM + ctg;
            #pragma unroll
            for (int ks = 0; ks < 4; ks++) {
                uint32_t b[2];
                b[0] = __float_as_uint(kp[ks * 8]);
                b[1] = __float_as_uint(kp[ks * 8 + 4]);
                mma_tf32(S[nt], qa[ks], b);
            }
        }

        // ---- bias add + online softmax
        float* pwarp = Pbuf + h * 32 * P_STRIDE + (qh * 16) * P_STRIDE;
        float mx1 = -1e30f, mx2 = -1e30f;
        #pragma unroll
        for (int nt = 0; nt < 8; nt++) {
            int col = nt * 8 + 2 * ctg;
            S[nt][0] += pwarp[gid * P_STRIDE + col];
            S[nt][1] += pwarp[gid * P_STRIDE + col + 1];
            S[nt][2] += pwarp[(gid + 8) * P_STRIDE + col];
            S[nt][3] += pwarp[(gid + 8) * P_STRIDE + col + 1];
            mx1 = fmaxf(mx1, fmaxf(S[nt][0], S[nt][1]));
            mx2 = fmaxf(mx2, fmaxf(S[nt][2], S[nt][3]));
        }
        mx1 = fmaxf(mx1, __shfl_xor_sync(~0u, mx1, 1));
        mx1 = fmaxf(mx1, __shfl_xor_sync(~0u, mx1, 2));
        mx2 = fmaxf(mx2, __shfl_xor_sync(~0u, mx2, 1));
        mx2 = fmaxf(mx2, __shfl_xor_sync(~0u, mx2, 2));
        float mn1 = fmaxf(m1, mx1), mn2 = fmaxf(m2, mx2);
        float al1 = __expf(m1 - mn1), al2 = __expf(m2 - mn2);
        float rs1 = 0.f, rs2 = 0.f;
        #pragma unroll
        for (int nt = 0; nt < 8; nt++) {
            float p0 = __expf(S[nt][0] - mn1);
            float p1 = __expf(S[nt][1] - mn1);
            float p2 = __expf(S[nt][2] - mn2);
            float p3 = __expf(S[nt][3] - mn2);
            rs1 += p0 + p1; rs2 += p2 + p3;
            int col = nt * 8 + 2 * ctg;
            pwarp[gid * P_STRIDE + col]           = __uint_as_float(f2tf32(p0));
            pwarp[gid * P_STRIDE + col + 1]       = __uint_as_float(f2tf32(p1));
            pwarp[(gid + 8) * P_STRIDE + col]     = __uint_as_float(f2tf32(p2));
            pwarp[(gid + 8) * P_STRIDE + col + 1] = __uint_as_float(f2tf32(p3));
        }
        rs1 += __shfl_xor_sync(~0u, rs1, 1); rs1 += __shfl_xor_sync(~0u, rs1, 2);
        rs2 += __shfl_xor_sync(~0u, rs2, 1); rs2 += __shfl_xor_sync(~0u, rs2, 2);
        l1 = l1 * al1 + rs1; l2 = l2 * al2 + rs2;
        m1 = mn1; m2 = mn2;
        #pragma unroll
        for (int on = 0; on < 4; on++) {
            O[on][0] *= al1; O[on][1] *= al1; O[on][2] *= al2; O[on][3] *= al2;
        }
        __syncwarp();

        // ---- PV (tf32 mma): O[16q x 32c] += P[16q x 64k] @ V[64k x 32c]
        #pragma unroll
        for (int on = 0; on < 4; on++) {
            #pragma unroll
            for (int ks = 0; ks < 8; ks++) {
                uint32_t a[4], b[2];
                const float* pp = pwarp + gid * P_STRIDE + ks * 8 + ctg;
                a[0] = __float_as_uint(pp[0]);
                a[1] = __float_as_uint(pp[8 * P_STRIDE]);
                a[2] = __float_as_uint(pp[4]);
                a[3] = __float_as_uint(pp[8 * P_STRIDE + 4]);
                const float* vp = Vsm + (ks * 8 + ctg) * V_STRIDE + h * HDIM + on * 8 + gid;
                b[0] = __float_as_uint(vp[0]);
                b[1] = __float_as_uint(vp[4 * V_STRIDE]);
                mma_tf32(O[on], a, b);
            }
        }
        // release Psm buffer to producers
        asm volatile("bar.arrive %0, 384;" :: "r"(3 + (t & 1)) : "memory");
    }

    // ---- epilogue: normalize, gate, store
    float r1 = 1.f / l1, r2 = 1.f / l2;
    int row1 = qg0 + qh * 16 + gid, row2 = row1 + 8;
    #pragma unroll
    for (int on = 0; on < 4; on++) {
        int col = h * HDIM + on * 8 + 2 * ctg;
        size_t i1 = (size_t)row1 * CDIM + col;
        size_t i2 = (size_t)row2 * CDIM + col;
        og[i1]     = O[on][0] * r1 * gg[i1];
        og[i1 + 1] = O[on][1] * r1 * gg[i1 + 1];
        og[i2]     = O[on][2] * r2 * gg[i2];
        og[i2 + 1] = O[on][3] * r2 * gg[i2 + 1];
    }
}

// ------------------------------ launch -------------------------------------
extern "C" void kernel_launch(void* const* d_in, const int* in_sizes, int n_in,
                              void* d_out, int out_size) {
    const float* a_q      = (const float*)d_in[0];
    const float* a_k      = (const float*)d_in[1];
    const float* z        = (const float*)d_in[2];
    const float* s_q      = (const float*)d_in[3];
    const float* s_k      = (const float*)d_in[4];
    const float* Wg_q     = (const float*)d_in[5];
    const float* bg_q     = (const float*)d_in[6];
    const float* Wb_q     = (const float*)d_in[7];
    const float* sscale_q = (const float*)d_in[8];
    const float* Wg_k     = (const float*)d_in[9];
    const float* bg_k     = (const float*)d_in[10];
    const float* Wb_k     = (const float*)d_in[11];
    const float* sscale_k = (const float*)d_in[12];
    const float* lnz      = (const float*)d_in[13];
    const float* Wq       = (const float*)d_in[14];
    const float* bq       = (const float*)d_in[15];
    const float* Wk       = (const float*)d_in[16];
    const float* Wv       = (const float*)d_in[17];
    const float* Wbias    = (const float*)d_in[18];
    const float* Wgate    = (const float*)d_in[19];
    const float* Wo       = (const float*)d_in[20];
    const float* Ws       = (const float*)d_in[21];
    const float* bs       = (const float*)d_in[22];

    float* scratch = nullptr;
    cudaGetSymbolAddress((void**)&scratch, g_scratch);
    const size_t SL = (size_t)NSEQ * CDIM;
    float* qbuf  = scratch + 0 * SL;
    float* gbuf  = scratch + 1 * SL;
    float* kbuf  = scratch + 2 * SL;
    float* vbuf  = scratch + 3 * SL;
    float* ogbuf = scratch + 4 * SL;
    float* biasw = scratch + 5 * SL;

    init_bias<<<1, 96>>>(lnz, Wbias, biasw);
    cudaMemcpyToSymbolAsync(c_bias, biasw, (CZ * NHEAD + NHEAD) * sizeof(float), 0,
                            cudaMemcpyDeviceToDevice, 0);

    cudaFuncSetAttribute(side_kernel<0>, cudaFuncAttributeMaxDynamicSharedMemorySize,
                         SMEM_SIDE_BYTES);
    cudaFuncSetAttribute(side_kernel<1>, cudaFuncAttributeMaxDynamicSharedMemorySize,
                         SMEM_SIDE_BYTES);
    cudaFuncSetAttribute(final_kernel, cudaFuncAttributeMaxDynamicSharedMemorySize,
                         SMEM_SIDE_BYTES);
    cudaFuncSetAttribute(attn_kernel, cudaFuncAttributeMaxDynamicSharedMemorySize,
                         SMEM_BYTES);

    side_kernel<0><<<NSEQ / 32, 256, SMEM_SIDE_BYTES>>>(
        a_q, s_q, sscale_q, Wg_q, bg_q, Wb_q, Wq, bq, Wgate, qbuf, gbuf);
    side_kernel<1><<<NSEQ / 32, 256, SMEM_SIDE_BYTES>>>(
        a_k, s_k, sscale_k, Wg_k, bg_k, Wb_k, Wk, nullptr, Wv, kbuf, vbuf);

    attn_kernel<<<NSEQ / 32, 384, SMEM_BYTES>>>(z, qbuf, kbuf, vbuf, gbuf, ogbuf);

    final_kernel<<<NSEQ / 32, 256, SMEM_SIDE_BYTES>>>(
        ogbuf, s_q, Wo, Ws, bs, (float*)d_out);
}

// round 8
// speedup vs baseline: 1.1835x; 1.0015x over previous
#include <cuda_runtime.h>
#include <cuda_bf16.h>
#include <cstdint>
#include <cstdio>

// ---------------------------------------------------------------------------
// AtomAttentionPairBias: B=1, Nq=Nk=4096, C=128, H=4, c=32, CZ=16  (all fp32)
//
//   1. init_bias: premultiply lnz*Wbias -> constant bank
//   2. side_kernel<Q/K>: LN -> AdaLN -> {q,gate} / {k,v}; split-tf32 mma
//   3. attn_kernel (WARP-SPECIALIZED): 8 consumer warps do flash attention
//      (tf32 mma QK^T / PV, online softmax); 4 producer warps stream z ONCE
//      and compute the fused LN(z)@Wbias bias for the NEXT tile into a
//      double-buffered Psm. Named-barrier full/empty handshake.
//   4. final_kernel: out = sigmoid(s_q@Ws+bs) * (og@Wo), split-tf32
// ---------------------------------------------------------------------------

#define NSEQ 4096
#define CDIM 128
#define NHEAD 4
#define HDIM 32
#define CZ 16
#define EPS 1e-5f
#define QK_SCALE 0.17677669529663687f   // 1/sqrt(32)

__device__ float g_scratch[6u * NSEQ * CDIM];

// c_bias[0..63]  = lnz[c] * Wbias[c][h]  (row-major [cz][h])
// c_bias[64..67] = per-head column sums of the above
__constant__ float c_bias[CZ * NHEAD + NHEAD];

__device__ __forceinline__ float sigmoidf_(float x) { return 1.f / (1.f + __expf(-x)); }

__device__ __forceinline__ uint32_t f2tf32(float x) {
    uint32_t y; asm("cvt.rna.tf32.f32 %0, %1;" : "=r"(y) : "f"(x)); return y;
}
__device__ __forceinline__ void mma_tf32(float* d, const uint32_t* a, const uint32_t* b) {
    asm volatile("mma.sync.aligned.m16n8k8.row.col.f32.tf32.tf32.f32 "
                 "{%0,%1,%2,%3}, {%4,%5,%6,%7}, {%8,%9}, {%0,%1,%2,%3};"
                 : "+f"(d[0]), "+f"(d[1]), "+f"(d[2]), "+f"(d[3])
                 : "r"(a[0]), "r"(a[1]), "r"(a[2]), "r"(a[3]), "r"(b[0]), "r"(b[1]));
}
__device__ __forceinline__ void cp16(float* dst, const float* src) {
    uint32_t d = (uint32_t)__cvta_generic_to_shared(dst);
    asm volatile("cp.async.cg.shared.global [%0], [%1], 16;" :: "r"(d), "l"(src));
}

// ------------------------------ init_bias ----------------------------------
__global__ void init_bias(const float* __restrict__ lnz, const float* __restrict__ wb,
                          float* __restrict__ out) {
    int t = threadIdx.x;
    if (t < 64) out[t] = lnz[t >> 2] * wb[t];
    if (t >= 64 && t < 68) {
        int h = t - 64;
        float s = 0.f;
        for (int c = 0; c < CZ; c++) s += lnz[c] * wb[c * 4 + h];
        out[t] = s;
    }
}

// ------------------- split-tf32 dual GEMM tile helper -----------------------
#define SA_STRIDE 132
#define SW_STRIDE 136

template<bool SAME_A>
__device__ __forceinline__ void gemm_dual(
    const float* __restrict__ sA1, const float* __restrict__ sA2,
    const float* __restrict__ gW1, const float* __restrict__ gW2,
    float* sW, int tid, float acc1[4][4], float acc2[4][4]) {

    const int lane = tid & 31, warp = tid >> 5;
    const int gid = lane >> 2, ctg = lane & 3;
    const int r0 = (warp & 1) * 16;
    const int c0 = (warp >> 1) * 32;

    #pragma unroll
    for (int nt = 0; nt < 4; nt++)
        #pragma unroll
        for (int j = 0; j < 4; j++) { acc1[nt][j] = 0.f; acc2[nt][j] = 0.f; }

    for (int kc = 0; kc < CDIM; kc += 64) {
        __syncthreads();   // protect sW from previous chunk's readers
        #pragma unroll
        for (int i = 0; i < 8; i++) {
            int e = tid + i * 256;
            int r = e >> 5, c4 = e & 31;
            cp16(sW + r * SW_STRIDE + c4 * 4, gW1 + (size_t)(kc + r) * CDIM + c4 * 4);
            cp16(sW + 64 * SW_STRIDE + r * SW_STRIDE + c4 * 4,
                 gW2 + (size_t)(kc + r) * CDIM + c4 * 4);
        }
        asm volatile("cp.async.commit_group;\ncp.async.wait_group 0;" ::: "memory");
        __syncthreads();

        #pragma unroll
        for (int ks = 0; ks < 8; ks++) {
            int kg = kc + ks * 8;
            uint32_t a1h[4], a1l[4], a2h[4], a2l[4];
            {
                const float* ap = sA1 + (r0 + gid) * SA_STRIDE + kg + ctg;
                float x;
                x = ap[0];               a1h[0] = f2tf32(x); a1l[0] = f2tf32(x - __uint_as_float(a1h[0]));
                x = ap[8 * SA_STRIDE];   a1h[1] = f2tf32(x); a1l[1] = f2tf32(x - __uint_as_float(a1h[1]));
                x = ap[4];               a1h[2] = f2tf32(x); a1l[2] = f2tf32(x - __uint_as_float(a1h[2]));
                x = ap[8 * SA_STRIDE+4]; a1h[3] = f2tf32(x); a1l[3] = f2tf32(x - __uint_as_float(a1h[3]));
            }
            if (!SAME_A) {
                const float* ap = sA2 + (r0 + gid) * SA_STRIDE + kg + ctg;
                float x;
                x = ap[0];               a2h[0] = f2tf32(x); a2l[0] = f2tf32(x - __uint_as_float(a2h[0]));
                x = ap[8 * SA_STRIDE];   a2h[1] = f2tf32(x); a2l[1] = f2tf32(x - __uint_as_float(a2h[1]));
                x = ap[4];               a2h[2] = f2tf32(x); a2l[2] = f2tf32(x - __uint_as_float(a2h[2]));
                x = ap[8 * SA_STRIDE+4]; a2h[3] = f2tf32(x); a2l[3] = f2tf32(x - __uint_as_float(a2h[3]));
            }
            #pragma unroll
            for (int nt = 0; nt < 4; nt++) {
                const float* bp = sW + (ks * 8 + ctg) * SW_STRIDE + c0 + nt * 8 + gid;
                uint32_t bh[2], bl[2];
                float b0 = bp[0], b1 = bp[4 * SW_STRIDE];
                bh[0] = f2tf32(b0); bl[0] = f2tf32(b0 - __uint_as_float(bh[0]));
                bh[1] = f2tf32(b1); bl[1] = f2tf32(b1 - __uint_as_float(bh[1]));
                mma_tf32(acc1[nt], a1h, bh);
                mma_tf32(acc1[nt], a1h, bl);
                mma_tf32(acc1[nt], a1l, bh);
                const float* bp2 = bp + 64 * SW_STRIDE;
                b0 = bp2[0]; b1 = bp2[4 * SW_STRIDE];
                bh[0] = f2tf32(b0); bl[0] = f2tf32(b0 - __uint_as_float(bh[0]));
                bh[1] = f2tf32(b1); bl[1] = f2tf32(b1 - __uint_as_float(bh[1]));
                if (SAME_A) {
                    mma_tf32(acc2[nt], a1h, bh);
                    mma_tf32(acc2[nt], a1h, bl);
                    mma_tf32(acc2[nt], a1l, bh);
                } else {
                    mma_tf32(acc2[nt], a2h, bh);
                    mma_tf32(acc2[nt], a2h, bl);
                    mma_tf32(acc2[nt], a2l, bh);
                }
            }
        }
    }
}

#define SMEM_SIDE_FLOATS (2 * 32 * SA_STRIDE + 2 * 64 * SW_STRIDE)
#define SMEM_SIDE_BYTES  (SMEM_SIDE_FLOATS * 4)

// ------------------------------ side kernel --------------------------------
template<int SIDE>
__global__ __launch_bounds__(256) void side_kernel(
    const float* __restrict__ ga, const float* __restrict__ gs,
    const float* __restrict__ sscale,
    const float* __restrict__ Wg, const float* __restrict__ bg,
    const float* __restrict__ Wb,
    const float* __restrict__ W1, const float* __restrict__ b1,
    const float* __restrict__ W2,
    float* __restrict__ out1, float* __restrict__ out2) {

    extern __shared__ float smem[];
    float* sA = smem;
    float* sS = smem + 32 * SA_STRIDE;
    float* sW = smem + 2 * 32 * SA_STRIDE;

    const int tid = threadIdx.x;
    const int lane = tid & 31, warp = tid >> 5;
    const int gid = lane >> 2, ctg = lane & 3;
    const int r0 = (warp & 1) * 16;
    const int c0 = (warp >> 1) * 32;
    const int row0 = blockIdx.x * 32;

    {
        float4 sc = ((const float4*)sscale)[lane];
        #pragma unroll
        for (int rr = 0; rr < 4; rr++) {
            int lrow = rr * 8 + warp;
            const float4* ap = (const float4*)(ga + (size_t)(row0 + lrow) * CDIM);
            const float4* sp = (const float4*)(gs + (size_t)(row0 + lrow) * CDIM);
            float4 av = ap[lane];
            float4 sv = sp[lane];
            float s1 = av.x + av.y + av.z + av.w;
            float s2 = av.x*av.x + av.y*av.y + av.z*av.z + av.w*av.w;
            float t1 = sv.x + sv.y + sv.z + sv.w;
            float t2 = sv.x*sv.x + sv.y*sv.y + sv.z*sv.z + sv.w*sv.w;
            #pragma unroll
            for (int o = 16; o > 0; o >>= 1) {
                s1 += __shfl_xor_sync(~0u, s1, o);
                s2 += __shfl_xor_sync(~0u, s2, o);
                t1 += __shfl_xor_sync(~0u, t1, o);
                t2 += __shfl_xor_sync(~0u, t2, o);
            }
            float ma = s1 * (1.f/CDIM);
            float ra = rsqrtf(s2 * (1.f/CDIM) - ma*ma + EPS);
            float ms = t1 * (1.f/CDIM);
            float rs = rsqrtf(t2 * (1.f/CDIM) - ms*ms + EPS);
            float* pa = sA + lrow * SA_STRIDE + lane * 4;
            float* ps = sS + lrow * SA_STRIDE + lane * 4;
            pa[0] = (av.x - ma) * ra; pa[1] = (av.y - ma) * ra;
            pa[2] = (av.z - ma) * ra; pa[3] = (av.w - ma) * ra;
            ps[0] = (sv.x - ms) * rs * sc.x; ps[1] = (sv.y - ms) * rs * sc.y;
            ps[2] = (sv.z - ms) * rs * sc.z; ps[3] = (sv.w - ms) * rs * sc.w;
        }
    }
    __syncthreads();

    float accG[4][4], accB[4][4];
    gemm_dual<true>(sS, sS, Wg, Wb, sW, tid, accG, accB);

    __syncthreads();
    #pragma unroll
    for (int nt = 0; nt < 4; nt++) {
        int col = c0 + nt * 8 + 2 * ctg;
        float bg0 = bg[col], bg1 = bg[col + 1];
        #pragma unroll
        for (int i = 0; i < 2; i++) {
            int lrow = r0 + gid + i * 8;
            float* pr = sS + lrow * SA_STRIDE + col;
            const float* pl = sA + lrow * SA_STRIDE + col;
            pr[0] = sigmoidf_(accG[nt][2*i]   + bg0) * pl[0] + accB[nt][2*i];
            pr[1] = sigmoidf_(accG[nt][2*i+1] + bg1) * pl[1] + accB[nt][2*i+1];
        }
    }

    float acc1[4][4], acc2[4][4];
    gemm_dual<true>(sS, sS, W1, W2, sW, tid, acc1, acc2);

    #pragma unroll
    for (int nt = 0; nt < 4; nt++) {
        int col = c0 + nt * 8 + 2 * ctg;
        float bb0 = 0.f, bb1 = 0.f;
        if (SIDE == 0) { bb0 = b1[col]; bb1 = b1[col + 1]; }
        #pragma unroll
        for (int i = 0; i < 2; i++) {
            int grow = row0 + r0 + gid + i * 8;
            size_t idx = (size_t)grow * CDIM + col;
            if (SIDE == 0) {
                out1[idx]     = (acc1[nt][2*i]   + bb0) * QK_SCALE;
                out1[idx + 1] = (acc1[nt][2*i+1] + bb1) * QK_SCALE;
                out2[idx]     = sigmoidf_(acc2[nt][2*i]);
                out2[idx + 1] = sigmoidf_(acc2[nt][2*i+1]);
            } else {
                out1[idx]     = acc1[nt][2*i];
                out1[idx + 1] = acc1[nt][2*i+1];
                out2[idx]     = acc2[nt][2*i];
                out2[idx + 1] = acc2[nt][2*i+1];
            }
        }
    }
}

// ------------------------------ final kernel -------------------------------
__global__ __launch_bounds__(256) void final_kernel(
    const float* __restrict__ og, const float* __restrict__ sq,
    const float* __restrict__ Wo, const float* __restrict__ Ws,
    const float* __restrict__ bs, float* __restrict__ out) {

    extern __shared__ float smem[];
    float* sA1 = smem;
    float* sA2 = smem + 32 * SA_STRIDE;
    float* sW  = smem + 2 * 32 * SA_STRIDE;

    const int tid = threadIdx.x;
    const int lane = tid & 31, warp = tid >> 5;
    const int gid = lane >> 2, ctg = lane & 3;
    const int r0 = (warp & 1) * 16;
    const int c0 = (warp >> 1) * 32;
    const int row0 = blockIdx.x * 32;

    #pragma unroll
    for (int i = 0; i < 4; i++) {
        int e = tid + i * 256;
        int r = e >> 5, c4 = e & 31;
        cp16(sA1 + r * SA_STRIDE + c4 * 4, og + (size_t)(row0 + r) * CDIM + c4 * 4);
        cp16(sA2 + r * SA_STRIDE + c4 * 4, sq + (size_t)(row0 + r) * CDIM + c4 * 4);
    }
    asm volatile("cp.async.commit_group;\ncp.async.wait_group 0;" ::: "memory");

    float acc1[4][4], acc2[4][4];
    gemm_dual<false>(sA1, sA2, Wo, Ws, sW, tid, acc1, acc2);

    #pragma unroll
    for (int nt = 0; nt < 4; nt++) {
        int col = c0 + nt * 8 + 2 * ctg;
        float b0 = bs[col], b1 = bs[col + 1];
        #pragma unroll
        for (int i = 0; i < 2; i++) {
            int grow = row0 + r0 + gid + i * 8;
            size_t idx = (size_t)grow * CDIM + col;
            out[idx]     = sigmoidf_(acc2[nt][2*i]   + b0) * acc1[nt][2*i];
            out[idx + 1] = sigmoidf_(acc2[nt][2*i+1] + b1) * acc1[nt][2*i+1];
        }
    }
}

// --------------------------- attention kernel ------------------------------
// 384 threads: warps 0-7 consumers (flash attention), warps 8-11 producers
// (z-bias for next tile into double-buffered Psm).
// Named barriers: 1,2 = full[0,1] (count 384); 3,4 = empty[0,1] (count 384);
//                 5 = consumer-only K/V reuse guard (count 256).
#define K_STRIDE 132
#define V_STRIDE 136
#define P_STRIDE 68
#define PBUF (NHEAD * 32 * P_STRIDE)
#define SMEM_FLOATS (64 * K_STRIDE + 64 * V_STRIDE + 2 * PBUF)
#define SMEM_BYTES  (SMEM_FLOATS * 4)
#define NTILES (NSEQ / 64)

__global__ __launch_bounds__(384, 1) void attn_kernel(
    const float* __restrict__ z,
    const float* __restrict__ gq, const float* __restrict__ gk,
    const float* __restrict__ gv, const float* __restrict__ gg,
    float* __restrict__ og) {

    extern __shared__ float smem[];
    float* Ksm = smem;
    float* Vsm = smem + 64 * K_STRIDE;
    float* Psm = Vsm + 64 * V_STRIDE;

    const int tid = threadIdx.x;
    const int qg0 = blockIdx.x * 32;

    if (tid >= 256) {
        // ======================= PRODUCER warps =======================
        const int ptid = tid - 256;
        const int kk0 = ptid & 63;           // key column within tile
        const int qq0 = ptid >> 6;           // 0 or 1; q = qq0 + 2*qi
        const float csum0 = c_bias[64], csum1 = c_bias[65];
        const float csum2 = c_bias[66], csum3 = c_bias[67];

        // 2-deep rolling z prefetch across the whole tile sequence
        float4 zb[2][4];
        #pragma unroll
        for (int u = 0; u < 2; u++) {
            const float4* zp = (const float4*)(z + ((size_t)(qg0 + qq0 + u * 2) * NSEQ + kk0) * CZ);
            zb[u][0] = zp[0]; zb[u][1] = zp[1]; zb[u][2] = zp[2]; zb[u][3] = zp[3];
        }

        for (int t = 0; t < NTILES; t++) {
            float* Pbuf = Psm + (t & 1) * PBUF;
            if (t >= 2)
                asm volatile("bar.sync %0, 384;" :: "r"(3 + (t & 1)) : "memory");
            const int kb = t * 64;
            #pragma unroll 4
            for (int qi = 0; qi < 16; qi++) {
                const int pb2 = qi & 1;      // t*16 even -> (u&1) == (qi&1)
                float4 zc[4] = { zb[pb2][0], zb[pb2][1], zb[pb2][2], zb[pb2][3] };
                // prefetch u+2
                {
                    int qin = (qi + 2) & 15;
                    int kbn = kb + (((qi + 2) >> 4) << 6);
                    if (kbn >= NSEQ) kbn = 0;   // tail: harmless valid reload
                    const float4* zn = (const float4*)(z + ((size_t)(qg0 + qq0 + qin * 2) * NSEQ + kbn + kk0) * CZ);
                    zb[pb2][0] = zn[0]; zb[pb2][1] = zn[1];
                    zb[pb2][2] = zn[2]; zb[pb2][3] = zn[3];
                }
                float s1 = 0.f, s2 = 0.f, d0 = 0.f, d1 = 0.f, d2 = 0.f, d3 = 0.f;
                #pragma unroll
                for (int j = 0; j < 4; j++) {
                    float4 v = zc[j];
                    int cb = j * 4;
                    s1 += v.x + v.y + v.z + v.w;
                    s2 += v.x*v.x + v.y*v.y + v.z*v.z + v.w*v.w;
                    d0 += v.x*c_bias[(cb+0)*4+0]; d1 += v.x*c_bias[(cb+0)*4+1];
                    d2 += v.x*c_bias[(cb+0)*4+2]; d3 += v.x*c_bias[(cb+0)*4+3];
                    d0 += v.y*c_bias[(cb+1)*4+0]; d1 += v.y*c_bias[(cb+1)*4+1];
                    d2 += v.y*c_bias[(cb+1)*4+2]; d3 += v.y*c_bias[(cb+1)*4+3];
                    d0 += v.z*c_bias[(cb+2)*4+0]; d1 += v.z*c_bias[(cb+2)*4+1];
                    d2 += v.z*c_bias[(cb+2)*4+2]; d3 += v.z*c_bias[(cb+2)*4+3];
                    d0 += v.w*c_bias[(cb+3)*4+0]; d1 += v.w*c_bias[(cb+3)*4+1];
                    d2 += v.w*c_bias[(cb+3)*4+2]; d3 += v.w*c_bias[(cb+3)*4+3];
                }
                float mm = s1 * (1.f/CZ);
                float rstd = rsqrtf(s2 * (1.f/CZ) - mm * mm + EPS);
                int q = qq0 + qi * 2;
                float* pb = Pbuf + q * P_STRIDE + kk0;
                pb[0 * 32 * P_STRIDE] = (d0 - mm * csum0) * rstd;
                pb[1 * 32 * P_STRIDE] = (d1 - mm * csum1) * rstd;
                pb[2 * 32 * P_STRIDE] = (d2 - mm * csum2) * rstd;
                pb[3 * 32 * P_STRIDE] = (d3 - mm * csum3) * rstd;
            }
            asm volatile("bar.arrive %0, 384;" :: "r"(1 + (t & 1)) : "memory");
        }
        return;
    }

    // ======================= CONSUMER warps =======================
    const int lane = tid & 31, warp = tid >> 5;
    const int h = warp >> 1, qh = warp & 1;
    const int gid = lane >> 2, ctg = lane & 3;

    // Q fragments (A of m16n8k8 tf32), q pre-scaled by 1/sqrt(c)
    uint32_t qa[4][4];
    {
        int r0 = qg0 + qh * 16 + gid;
        const float* qp = gq + (size_t)r0 * CDIM + h * HDIM + ctg;
        #pragma unroll
        for (int ks = 0; ks < 4; ks++) {
            qa[ks][0] = f2tf32(qp[ks*8]);
            qa[ks][1] = f2tf32(qp[8*CDIM + ks*8]);
            qa[ks][2] = f2tf32(qp[ks*8 + 4]);
            qa[ks][3] = f2tf32(qp[8*CDIM + ks*8 + 4]);
        }
    }

    float O[4][4];
    #pragma unroll
    for (int i = 0; i < 4; i++) { O[i][0]=O[i][1]=O[i][2]=O[i][3]=0.f; }
    float m1 = -1e30f, m2 = -1e30f, l1 = 0.f, l2 = 0.f;

    for (int t = 0; t < NTILES; t++) {
        const int kb = t * 64;
        // all consumers done reading previous K/V tile
        asm volatile("bar.sync 5, 256;" ::: "memory");

        // prefetch K/V tile (256 consumer threads)
        #pragma unroll
        for (int i = 0; i < 8; i++) {
            int e = tid + i * 256;
            int r = e >> 5, c4 = e & 31;
            cp16(Ksm + r * K_STRIDE + c4 * 4, gk + (size_t)(kb + r) * CDIM + c4 * 4);
        }
        #pragma unroll
        for (int i = 0; i < 8; i++) {
            int e = tid + i * 256;
            int r = e >> 5, c4 = e & 31;
            cp16(Vsm + r * V_STRIDE + c4 * 4, gv + (size_t)(kb + r) * CDIM + c4 * 4);
        }
        asm volatile("cp.async.commit_group;\ncp.async.wait_group 0;" ::: "memory");

        // wait for producers' bias tile (also rendezvous: everyone's cp.async done)
        asm volatile("bar.sync %0, 384;" :: "r"(1 + (t & 1)) : "memory");
        float* Pbuf = Psm + (t & 1) * PBUF;

        // ---- QK^T (tf32 mma): S[16q x 64k] per warp
        float S[8][4];
        #pragma unroll
        for (int nt = 0; nt < 8; nt++) {
            S[nt][0] = S[nt][1] = S[nt][2] = S[nt][3] = 0.f;
            const float* kp = Ksm + (nt * 8 + gid) * K_STRIDE + h * HDIM + ctg;
            #pragma unroll
            for (int ks = 0; ks < 4; ks++) {
                uint32_t b[2];
                b[0] = __float_as_uint(kp[ks * 8]);
                b[1] = __float_as_uint(kp[ks * 8 + 4]);
                mma_tf32(S[nt], qa[ks], b);
            }
        }

        // ---- bias add + online softmax
        float* pwarp = Pbuf + h * 32 * P_STRIDE + (qh * 16) * P_STRIDE;
        float mx1 = -1e30f, mx2 = -1e30f;
        #pragma unroll
        for (int nt = 0; nt < 8; nt++) {
            int col = nt * 8 + 2 * ctg;
            S[nt][0] += pwarp[gid * P_STRIDE + col];
            S[nt][1] += pwarp[gid * P_STRIDE + col + 1];
            S[nt][2] += pwarp[(gid + 8) * P_STRIDE + col];
            S[nt][3] += pwarp[(gid + 8) * P_STRIDE + col + 1];
            mx1 = fmaxf(mx1, fmaxf(S[nt][0], S[nt][1]));
            mx2 = fmaxf(mx2, fmaxf(S[nt][2], S[nt][3]));
        }
        mx1 = fmaxf(mx1, __shfl_xor_sync(~0u, mx1, 1));
        mx1 = fmaxf(mx1, __shfl_xor_sync(~0u, mx1, 2));
        mx2 = fmaxf(mx2, __shfl_xor_sync(~0u, mx2, 1));
        mx2 = fmaxf(mx2, __shfl_xor_sync(~0u, mx2, 2));
        float mn1 = fmaxf(m1, mx1), mn2 = fmaxf(m2, mx2);
        float al1 = __expf(m1 - mn1), al2 = __expf(m2 - mn2);
        float rs1 = 0.f, rs2 = 0.f;
        #pragma unroll
        for (int nt = 0; nt < 8; nt++) {
            float p0 = __expf(S[nt][0] - mn1);
            float p1 = __expf(S[nt][1] - mn1);
            float p2 = __expf(S[nt][2] - mn2);
            float p3 = __expf(S[nt][3] - mn2);
            rs1 += p0 + p1; rs2 += p2 + p3;
            int col = nt * 8 + 2 * ctg;
            pwarp[gid * P_STRIDE + col]           = __uint_as_float(f2tf32(p0));
            pwarp[gid * P_STRIDE + col + 1]       = __uint_as_float(f2tf32(p1));
            pwarp[(gid + 8) * P_STRIDE + col]     = __uint_as_float(f2tf32(p2));
            pwarp[(gid + 8) * P_STRIDE + col + 1] = __uint_as_float(f2tf32(p3));
        }
        rs1 += __shfl_xor_sync(~0u, rs1, 1); rs1 += __shfl_xor_sync(~0u, rs1, 2);
        rs2 += __shfl_xor_sync(~0u, rs2, 1); rs2 += __shfl_xor_sync(~0u, rs2, 2);
        l1 = l1 * al1 + rs1; l2 = l2 * al2 + rs2;
        m1 = mn1; m2 = mn2;
        #pragma unroll
        for (int on = 0; on < 4; on++) {
            O[on][0] *= al1; O[on][1] *= al1; O[on][2] *= al2; O[on][3] *= al2;
        }
        __syncwarp();

        // ---- PV (tf32 mma): O[16q x 32c] += P[16q x 64k] @ V[64k x 32c]
        #pragma unroll
        for (int on = 0; on < 4; on++) {
            #pragma unroll
            for (int ks = 0; ks < 8; ks++) {
                uint32_t a[4], b[2];
                const float* pp = pwarp + gid * P_STRIDE + ks * 8 + ctg;
                a[0] = __float_as_uint(pp[0]);
                a[1] = __float_as_uint(pp[8 * P_STRIDE]);
                a[2] = __float_as_uint(pp[4]);
                a[3] = __float_as_uint(pp[8 * P_STRIDE + 4]);
                const float* vp = Vsm + (ks * 8 + ctg) * V_STRIDE + h * HDIM + on * 8 + gid;
                b[0] = __float_as_uint(vp[0]);
                b[1] = __float_as_uint(vp[4 * V_STRIDE]);
                mma_tf32(O[on], a, b);
            }
        }
        // release Psm buffer to producers
        asm volatile("bar.arrive %0, 384;" :: "r"(3 + (t & 1)) : "memory");
    }

    // ---- epilogue: normalize, gate, store
    float r1 = 1.f / l1, r2 = 1.f / l2;
    int row1 = qg0 + qh * 16 + gid, row2 = row1 + 8;
    #pragma unroll
    for (int on = 0; on < 4; on++) {
        int col = h * HDIM + on * 8 + 2 * ctg;
        size_t i1 = (size_t)row1 * CDIM + col;
        size_t i2 = (size_t)row2 * CDIM + col;
        og[i1]     = O[on][0] * r1 * gg[i1];
        og[i1 + 1] = O[on][1] * r1 * gg[i1 + 1];
        og[i2]     = O[on][2] * r2 * gg[i2];
        og[i2 + 1] = O[on][3] * r2 * gg[i2 + 1];
    }
}

// ------------------------------ launch -------------------------------------
extern "C" void kernel_launch(void* const* d_in, const int* in_sizes, int n_in,
                              void* d_out, int out_size) {
    const float* a_q      = (const float*)d_in[0];
    const float* a_k      = (const float*)d_in[1];
    const float* z        = (const float*)d_in[2];
    const float* s_q      = (const float*)d_in[3];
    const float* s_k      = (const float*)d_in[4];
    const float* Wg_q     = (const float*)d_in[5];
    const float* bg_q     = (const float*)d_in[6];
    const float* Wb_q     = (const float*)d_in[7];
    const float* sscale_q = (const float*)d_in[8];
    const float* Wg_k     = (const float*)d_in[9];
    const float* bg_k     = (const float*)d_in[10];
    const float* Wb_k     = (const float*)d_in[11];
    const float* sscale_k = (const float*)d_in[12];
    const float* lnz      = (const float*)d_in[13];
    const float* Wq       = (const float*)d_in[14];
    const float* bq       = (const float*)d_in[15];
    const float* Wk       = (const float*)d_in[16];
    const float* Wv       = (const float*)d_in[17];
    const float* Wbias    = (const float*)d_in[18];
    const float* Wgate    = (const float*)d_in[19];
    const float* Wo       = (const float*)d_in[20];
    const float* Ws       = (const float*)d_in[21];
    const float* bs       = (const float*)d_in[22];

    float* scratch = nullptr;
    cudaGetSymbolAddress((void**)&scratch, g_scratch);
    const size_t SL = (size_t)NSEQ * CDIM;
    float* qbuf  = scratch + 0 * SL;
    float* gbuf  = scratch + 1 * SL;
    float* kbuf  = scratch + 2 * SL;
    float* vbuf  = scratch + 3 * SL;
    float* ogbuf = scratch + 4 * SL;
    float* biasw = scratch + 5 * SL;

    init_bias<<<1, 96>>>(lnz, Wbias, biasw);
    cudaMemcpyToSymbolAsync(c_bias, biasw, (CZ * NHEAD + NHEAD) * sizeof(float), 0,
                            cudaMemcpyDeviceToDevice, 0);

    cudaFuncSetAttribute(side_kernel<0>, cudaFuncAttributeMaxDynamicSharedMemorySize,
                         SMEM_SIDE_BYTES);
    cudaFuncSetAttribute(side_kernel<1>, cudaFuncAttributeMaxDynamicSharedMemorySize,
                         SMEM_SIDE_BYTES);
    cudaFuncSetAttribute(final_kernel, cudaFuncAttributeMaxDynamicSharedMemorySize,
                         SMEM_SIDE_BYTES);
    cudaFuncSetAttribute(attn_kernel, cudaFuncAttributeMaxDynamicSharedMemorySize,
                         SMEM_BYTES);

    side_kernel<0><<<NSEQ / 32, 256, SMEM_SIDE_BYTES>>>(
        a_q, s_q, sscale_q, Wg_q, bg_q, Wb_q, Wq, bq, Wgate, qbuf, gbuf);
    side_kernel<1><<<NSEQ / 32, 256, SMEM_SIDE_BYTES>>>(
        a_k, s_k, sscale_k, Wg_k, bg_k, Wb_k, Wk, nullptr, Wv, kbuf, vbuf);

    attn_kernel<<<NSEQ / 32, 384, SMEM_BYTES>>>(z, qbuf, kbuf, vbuf, gbuf, ogbuf);

    final_kernel<<<NSEQ / 32, 256, SMEM_SIDE_BYTES>>>(
        ogbuf, s_q, Wo, Ws, bs, (float*)d_out);
}